// round 2
// baseline (speedup 1.0000x reference)
#include <cuda_runtime.h>
#include <math.h>

#define NN 50000
#define EE 800000
#define NF 128
#define NH 64
#define NC 40

// ---- scratch (static device globals; no allocation in kernel_launch) ----
__device__ float g_A[NN * NF];    // spmm output (layers 1 & 2)
__device__ float g_H0[NN * NF];   // relu((A*AM)@W0+b0)
__device__ float g_H1[NN * NH];   // relu((A*AM)@W1+b1)
__device__ float g_C[NN * NH];    // spmm3 output
__device__ int   g_hist[NN];
__device__ int   g_rowptr[NN + 1];
__device__ int   g_cursor[NN];
__device__ int   g_scol[EE];
__device__ float g_svZ[EE];       // adjZ_vals[e] * M[col[e]]  (shared by layers 1 & 2)
__device__ float g_sv[EE];        // adj_vals[e]               (layer 3)

// ---------------- CSR build ----------------
__global__ void zero_hist_kernel() {
    int i = blockIdx.x * blockDim.x + threadIdx.x;
    if (i < NN) g_hist[i] = 0;
}

__global__ void hist_kernel(const int* __restrict__ row) {
    int e = blockIdx.x * blockDim.x + threadIdx.x;
    if (e < EE) atomicAdd(&g_hist[row[e]], 1);
}

// single-block exclusive scan over g_hist -> g_rowptr, g_cursor
__global__ void scan_kernel() {
    __shared__ int ssum[1024];
    const int CH = (NN + 1023) / 1024;   // 49
    int t = threadIdx.x;
    int base = t * CH;
    int local = 0;
    for (int i = 0; i < CH; i++) {
        int idx = base + i;
        if (idx < NN) local += g_hist[idx];
    }
    ssum[t] = local;
    __syncthreads();
    // Hillis-Steele inclusive scan
    for (int off = 1; off < 1024; off <<= 1) {
        int v = (t >= off) ? ssum[t - off] : 0;
        __syncthreads();
        ssum[t] += v;
        __syncthreads();
    }
    int run = ssum[t] - local;  // exclusive prefix for this chunk
    for (int i = 0; i < CH; i++) {
        int idx = base + i;
        if (idx < NN) {
            g_rowptr[idx] = run;
            g_cursor[idx] = run;
            run += g_hist[idx];
        }
    }
    if (t == 0) g_rowptr[NN] = EE;
}

__global__ void scatter_kernel(const int* __restrict__ row, const int* __restrict__ col,
                               const float* __restrict__ adj, const float* __restrict__ adjZ,
                               const float* __restrict__ M) {
    int e = blockIdx.x * blockDim.x + threadIdx.x;
    if (e >= EE) return;
    int c = col[e];
    int pos = atomicAdd(&g_cursor[row[e]], 1);
    g_scol[pos] = c;
    g_svZ[pos]  = adjZ[e] * M[c];   // fold M[col] once for both PaGConv layers
    g_sv[pos]   = adj[e];
}

// ---------------- SPMM: one warp per row, register accumulation ----------------
template <int FEAT, bool USEZ>
__global__ void spmm_kernel(const float* __restrict__ X, float* __restrict__ out) {
    int r = (blockIdx.x * blockDim.x + threadIdx.x) >> 5;
    if (r >= NN) return;
    int lane = threadIdx.x & 31;
    int s = g_rowptr[r];
    int e = g_rowptr[r + 1];
    const float* vals = USEZ ? g_svZ : g_sv;

    if (FEAT == 128) {
        const float4* X4 = (const float4*)X;
        float4 acc = make_float4(0.f, 0.f, 0.f, 0.f);
        for (int i = s; i < e; i++) {
            int c = __ldg(&g_scol[i]);
            float w = __ldg(&vals[i]);
            float4 xv = __ldg(&X4[c * 32 + lane]);
            acc.x += w * xv.x; acc.y += w * xv.y;
            acc.z += w * xv.z; acc.w += w * xv.w;
        }
        ((float4*)out)[r * 32 + lane] = acc;
    } else {  // FEAT == 64
        const float2* X2 = (const float2*)X;
        float2 acc = make_float2(0.f, 0.f);
        for (int i = s; i < e; i++) {
            int c = __ldg(&g_scol[i]);
            float w = __ldg(&vals[i]);
            float2 xv = __ldg(&X2[c * 32 + lane]);
            acc.x += w * xv.x; acc.y += w * xv.y;
        }
        ((float2*)out)[r * 32 + lane] = acc;
    }
}

// ---------------- register-tiled fp32 GEMM: out = relu((A*AM) @ W + b) ----------------
template <int KIN, int NOUT, int TM, int TN>
__global__ void gemm_bias_relu(const float* __restrict__ A, const float* __restrict__ AM,
                               const float* __restrict__ W, const float* __restrict__ bias,
                               float* __restrict__ out) {
    constexpr int BK  = 16;
    constexpr int NCT = NOUT / TN;   // col-thread groups
    constexpr int NRT = 256 / NCT;   // row-thread groups
    constexpr int BM  = NRT * TM;    // rows per block (=64 for both configs)

    __shared__ __align__(16) float As[BM][BK];
    __shared__ __align__(16) float Ws[BK][NOUT];

    int tid  = threadIdx.x;
    int ct   = tid % NCT;
    int rt   = tid / NCT;
    int col0 = ct * TN;
    int row0 = rt * TM;
    int br   = blockIdx.x * BM;

    float acc[TM][TN];
#pragma unroll
    for (int i = 0; i < TM; i++)
#pragma unroll
        for (int j = 0; j < TN; j++) acc[i][j] = 0.f;

    for (int kk = 0; kk < KIN; kk += BK) {
        // A tile (BM x BK), fused row-scale by AM
#pragma unroll
        for (int i = tid; i < BM * BK / 4; i += 256) {
            int m  = i / (BK / 4);
            int k4 = (i % (BK / 4)) * 4;
            int gr = br + m;
            float4 v = make_float4(0.f, 0.f, 0.f, 0.f);
            if (gr < NN) {
                v = *(const float4*)&A[gr * KIN + kk + k4];
                float am = AM[gr];
                v.x *= am; v.y *= am; v.z *= am; v.w *= am;
            }
            *(float4*)&As[m][k4] = v;
        }
        // W tile (BK x NOUT)
#pragma unroll
        for (int i = tid; i < BK * NOUT / 4; i += 256) {
            int k  = i / (NOUT / 4);
            int n4 = (i % (NOUT / 4)) * 4;
            *(float4*)&Ws[k][n4] = *(const float4*)&W[(kk + k) * NOUT + n4];
        }
        __syncthreads();

#pragma unroll
        for (int k = 0; k < BK; k++) {
            float a[TM], wv[TN];
#pragma unroll
            for (int j = 0; j < TN; j++) wv[j] = Ws[k][col0 + j];
#pragma unroll
            for (int i = 0; i < TM; i++) a[i] = As[row0 + i][k];
#pragma unroll
            for (int i = 0; i < TM; i++)
#pragma unroll
                for (int j = 0; j < TN; j++) acc[i][j] += a[i] * wv[j];
        }
        __syncthreads();
    }

#pragma unroll
    for (int i = 0; i < TM; i++) {
        int gr = br + row0 + i;
        if (gr < NN) {
#pragma unroll
            for (int j = 0; j < TN; j++) {
                float v = acc[i][j] + bias[col0 + j];
                out[gr * NOUT + col0 + j] = fmaxf(v, 0.f);
            }
        }
    }
}

// ---------------- fused [1,64]@[64,40] + bias + log_softmax, one warp per row ----------------
__global__ void final_kernel(const float* __restrict__ H, const float* __restrict__ W2,
                             const float* __restrict__ b2, float* __restrict__ out) {
    __shared__ float W2s[NH * NC];
    __shared__ float b2s[NC];
    int tid = threadIdx.x;
    for (int i = tid; i < NH * NC; i += blockDim.x) W2s[i] = W2[i];
    if (tid < NC) b2s[tid] = b2[tid];
    __syncthreads();

    int r = blockIdx.x * (blockDim.x >> 5) + (tid >> 5);
    if (r >= NN) return;
    int lane = tid & 31;

    float2 hv = ((const float2*)H)[r * 32 + lane];  // h[2*lane], h[2*lane+1]
    float acc0 = 0.f, acc1 = 0.f;
    int l8 = 32 + (lane & 7);
#pragma unroll
    for (int k = 0; k < NH; k++) {
        float hk = __shfl_sync(0xffffffffu, (k & 1) ? hv.y : hv.x, k >> 1);
        acc0 += hk * W2s[k * NC + lane];   // cols 0..31
        acc1 += hk * W2s[k * NC + l8];     // cols 32..39 (valid on lanes 0..7)
    }
    float v0 = acc0 + b2s[lane];
    float v1 = acc1 + b2s[l8];
    bool has1 = (lane < 8);

    float m = fmaxf(v0, has1 ? v1 : -INFINITY);
#pragma unroll
    for (int o = 16; o > 0; o >>= 1) m = fmaxf(m, __shfl_xor_sync(0xffffffffu, m, o));
    float s = expf(v0 - m) + (has1 ? expf(v1 - m) : 0.f);
#pragma unroll
    for (int o = 16; o > 0; o >>= 1) s += __shfl_xor_sync(0xffffffffu, s, o);
    float lse = m + logf(s);

    out[r * NC + lane] = v0 - lse;
    if (has1) out[r * NC + 32 + lane] = v1 - lse;
}

// ---------------- launch ----------------
extern "C" void kernel_launch(void* const* d_in, const int* in_sizes, int n_in,
                              void* d_out, int out_size) {
    const float* x    = (const float*)d_in[0];
    const float* M    = (const float*)d_in[1];
    const float* AM   = (const float*)d_in[2];
    const float* adj  = (const float*)d_in[3];
    const float* adjZ = (const float*)d_in[4];
    const float* W0   = (const float*)d_in[5];
    const float* b0   = (const float*)d_in[6];
    const float* W1   = (const float*)d_in[7];
    const float* b1   = (const float*)d_in[8];
    const float* W2   = (const float*)d_in[9];
    const float* b2   = (const float*)d_in[10];
    const int*   row  = (const int*)d_in[11];
    const int*   col  = (const int*)d_in[12];
    float* out = (float*)d_out;

    void *pA, *pH0, *pH1, *pC;
    cudaGetSymbolAddress(&pA,  g_A);
    cudaGetSymbolAddress(&pH0, g_H0);
    cudaGetSymbolAddress(&pH1, g_H1);
    cudaGetSymbolAddress(&pC,  g_C);
    float* A  = (float*)pA;
    float* H0 = (float*)pH0;
    float* H1 = (float*)pH1;
    float* C  = (float*)pC;

    // CSR build (per launch; graph-replay safe)
    zero_hist_kernel<<<(NN + 255) / 256, 256>>>();
    hist_kernel<<<(EE + 255) / 256, 256>>>(row);
    scan_kernel<<<1, 1024>>>();
    scatter_kernel<<<(EE + 255) / 256, 256>>>(row, col, adj, adjZ, M);

    const int spmmBlocks = (NN + 7) / 8;          // 8 warps/block
    const int gemmBlocks = (NN + 63) / 64;        // BM=64

    // layer 0: h = relu((spmm(adjZ, M*x) * AM) @ W0 + b0)
    spmm_kernel<128, true><<<spmmBlocks, 256>>>(x, A);
    gemm_bias_relu<128, 128, 8, 4><<<gemmBlocks, 256>>>(A, AM, W0, b0, H0);

    // layer 1: h = relu((spmm(adjZ, M*h) * AM) @ W1 + b1)
    spmm_kernel<128, true><<<spmmBlocks, 256>>>(H0, A);
    gemm_bias_relu<128, 64, 4, 4><<<gemmBlocks, 256>>>(A, AM, W1, b1, H1);

    // layer 2: log_softmax(spmm(adj, h) @ W2 + b2)
    spmm_kernel<64, false><<<spmmBlocks, 256>>>(H1, C);
    final_kernel<<<(NN + 7) / 8, 256>>>(C, W2, b2, out);
}

// round 3
// speedup vs baseline: 1.0282x; 1.0282x over previous
#include <cuda_runtime.h>
#include <math.h>

#define NN 50000
#define EE 800000
#define NF 128
#define NH 64
#define NC 40

// ---- scratch (static device globals; no allocation in kernel_launch) ----
struct __align__(16) Edge { int col; float vZ; float v; float pad; };

__device__ float g_A[NN * NF];    // spmm output (layers 0 & 1), pre-scaled by AM
__device__ float g_H0[NN * NF];   // relu(A@W0+b0)
__device__ float g_H1[NN * NH];   // relu(A@W1+b1)
__device__ int   g_hist[NN];
__device__ int   g_rowptr[NN + 1];
__device__ int   g_cursor[NN];
__device__ Edge  g_edges[EE];     // sorted-by-row edge records (16B packed)

// ---------------- CSR build ----------------
__global__ void hist_kernel(const int* __restrict__ row) {
    int e = blockIdx.x * blockDim.x + threadIdx.x;
    if (e < EE) atomicAdd(&g_hist[row[e]], 1);
}

// single-block exclusive scan over g_hist -> g_rowptr, g_cursor
__global__ void scan_kernel() {
    __shared__ int ssum[1024];
    const int CH = (NN + 1023) / 1024;   // 49
    int t = threadIdx.x;
    int base = t * CH;
    int local = 0;
    for (int i = 0; i < CH; i++) {
        int idx = base + i;
        if (idx < NN) local += g_hist[idx];
    }
    ssum[t] = local;
    __syncthreads();
    for (int off = 1; off < 1024; off <<= 1) {
        int v = (t >= off) ? ssum[t - off] : 0;
        __syncthreads();
        ssum[t] += v;
        __syncthreads();
    }
    int run = ssum[t] - local;
    for (int i = 0; i < CH; i++) {
        int idx = base + i;
        if (idx < NN) {
            g_rowptr[idx] = run;
            g_cursor[idx] = run;
            run += g_hist[idx];
        }
    }
    if (t == 0) g_rowptr[NN] = EE;
}

__global__ void scatter_kernel(const int* __restrict__ row, const int* __restrict__ col,
                               const float* __restrict__ adj, const float* __restrict__ adjZ,
                               const float* __restrict__ M) {
    int e = blockIdx.x * blockDim.x + threadIdx.x;
    if (e >= EE) return;
    int c = col[e];
    int pos = atomicAdd(&g_cursor[row[e]], 1);
    float4 ed;
    ed.x = __int_as_float(c);
    ed.y = adjZ[e] * M[c];   // fold M[col] once for both PaGConv layers
    ed.z = adj[e];
    ed.w = 0.f;
    *(float4*)&g_edges[pos] = ed;   // single 16B store (was 3x scattered 4B)
}

// ---------------- SPMM 128-feat: one warp per row, AM fused into epilogue ----------------
__global__ void spmm128_kernel(const float* __restrict__ X, const float* __restrict__ AM,
                               float* __restrict__ out) {
    int r = (blockIdx.x * blockDim.x + threadIdx.x) >> 5;
    if (r >= NN) return;
    int lane = threadIdx.x & 31;
    int s = g_rowptr[r];
    int e = g_rowptr[r + 1];
    const float4* X4 = (const float4*)X;

    float4 acc = make_float4(0.f, 0.f, 0.f, 0.f);
    int i = s;
    for (; i + 2 <= e; i += 2) {   // 2-way unroll: double loads in flight vs L2 latency
        float4 e0 = __ldg((const float4*)&g_edges[i]);
        float4 e1 = __ldg((const float4*)&g_edges[i + 1]);
        int   c0 = __float_as_int(e0.x);
        int   c1 = __float_as_int(e1.x);
        float w0 = e0.y;
        float w1 = e1.y;
        float4 x0 = __ldg(&X4[c0 * 32 + lane]);
        float4 x1 = __ldg(&X4[c1 * 32 + lane]);
        acc.x += w0 * x0.x; acc.y += w0 * x0.y; acc.z += w0 * x0.z; acc.w += w0 * x0.w;
        acc.x += w1 * x1.x; acc.y += w1 * x1.y; acc.z += w1 * x1.z; acc.w += w1 * x1.w;
    }
    if (i < e) {
        float4 e0 = __ldg((const float4*)&g_edges[i]);
        int   c0 = __float_as_int(e0.x);
        float w0 = e0.y;
        float4 x0 = __ldg(&X4[c0 * 32 + lane]);
        acc.x += w0 * x0.x; acc.y += w0 * x0.y; acc.z += w0 * x0.z; acc.w += w0 * x0.w;
    }
    float am = __ldg(&AM[r]);
    acc.x *= am; acc.y *= am; acc.z *= am; acc.w *= am;
    ((float4*)out)[r * 32 + lane] = acc;
}

// ---------------- register-tiled fp32 GEMM: out = relu(A @ W + b) ----------------
template <int KIN, int NOUT, int TM>
__global__ void gemm_bias_relu(const float* __restrict__ A,
                               const float* __restrict__ W, const float* __restrict__ bias,
                               float* __restrict__ out) {
    constexpr int TN  = 4;
    constexpr int BK  = 16;
    constexpr int NCT = NOUT / TN;   // col-thread groups (32 or 16)
    constexpr int NRT = 256 / NCT;
    constexpr int BM  = NRT * TM;    // 64 for both configs

    __shared__ __align__(16) float As[BM][BK];
    __shared__ __align__(16) float Ws[BK][NOUT];

    int tid  = threadIdx.x;
    int ct   = tid % NCT;
    int rt   = tid / NCT;
    int col0 = ct * TN;
    int row0 = rt * TM;
    int br   = blockIdx.x * BM;

    float acc[TM][TN];
#pragma unroll
    for (int i = 0; i < TM; i++)
#pragma unroll
        for (int j = 0; j < TN; j++) acc[i][j] = 0.f;

    for (int kk = 0; kk < KIN; kk += BK) {
        // A tile (BM x BK): 256 float4 loads, one per thread
        {
            int i  = tid;
            int m  = i / (BK / 4);
            int k4 = (i % (BK / 4)) * 4;
            int gr = br + m;
            float4 v = make_float4(0.f, 0.f, 0.f, 0.f);
            if (gr < NN) v = *(const float4*)&A[gr * KIN + kk + k4];
            *(float4*)&As[m][k4] = v;
        }
        // W tile (BK x NOUT)
#pragma unroll
        for (int i = tid; i < BK * NOUT / 4; i += 256) {
            int k  = i / (NOUT / 4);
            int n4 = (i % (NOUT / 4)) * 4;
            *(float4*)&Ws[k][n4] = *(const float4*)&W[(kk + k) * NOUT + n4];
        }
        __syncthreads();

#pragma unroll
        for (int k = 0; k < BK; k++) {
            float4 w4 = *(const float4*)&Ws[k][col0];   // LDS.128, conflict-free
            float a[TM];
#pragma unroll
            for (int i = 0; i < TM; i++) a[i] = As[row0 + i][k];  // broadcast
#pragma unroll
            for (int i = 0; i < TM; i++) {
                acc[i][0] += a[i] * w4.x;
                acc[i][1] += a[i] * w4.y;
                acc[i][2] += a[i] * w4.z;
                acc[i][3] += a[i] * w4.w;
            }
        }
        __syncthreads();
    }

#pragma unroll
    for (int i = 0; i < TM; i++) {
        int gr = br + row0 + i;
        if (gr < NN) {
            float4 o;
            o.x = fmaxf(acc[i][0] + bias[col0 + 0], 0.f);
            o.y = fmaxf(acc[i][1] + bias[col0 + 1], 0.f);
            o.z = fmaxf(acc[i][2] + bias[col0 + 2], 0.f);
            o.w = fmaxf(acc[i][3] + bias[col0 + 3], 0.f);
            *(float4*)&out[gr * NOUT + col0] = o;
        }
    }
}

// ---- fused layer 2: spmm64(adj) + [1,64]@[64,40] + bias + log_softmax, one warp/row ----
__global__ void spmm64_final_kernel(const float* __restrict__ H,
                                    const float* __restrict__ W2,
                                    const float* __restrict__ b2,
                                    float* __restrict__ out) {
    __shared__ float W2s[NH * NC];
    __shared__ float b2s[NC];
    int tid = threadIdx.x;
    for (int i = tid; i < NH * NC; i += blockDim.x) W2s[i] = W2[i];
    if (tid < NC) b2s[tid] = b2[tid];
    __syncthreads();

    int r = blockIdx.x * (blockDim.x >> 5) + (tid >> 5);
    if (r >= NN) return;
    int lane = tid & 31;
    int s = g_rowptr[r];
    int e = g_rowptr[r + 1];
    const float2* X2 = (const float2*)H;

    // SPMM over adj (plain vals), 64 feats -> float2 per lane = h[2*lane], h[2*lane+1]
    float2 hv = make_float2(0.f, 0.f);
    int i = s;
    for (; i + 2 <= e; i += 2) {
        float4 e0 = __ldg((const float4*)&g_edges[i]);
        float4 e1 = __ldg((const float4*)&g_edges[i + 1]);
        int   c0 = __float_as_int(e0.x);
        int   c1 = __float_as_int(e1.x);
        float w0 = e0.z;
        float w1 = e1.z;
        float2 x0 = __ldg(&X2[c0 * 32 + lane]);
        float2 x1 = __ldg(&X2[c1 * 32 + lane]);
        hv.x += w0 * x0.x; hv.y += w0 * x0.y;
        hv.x += w1 * x1.x; hv.y += w1 * x1.y;
    }
    if (i < e) {
        float4 e0 = __ldg((const float4*)&g_edges[i]);
        int   c0 = __float_as_int(e0.x);
        float w0 = e0.z;
        float2 x0 = __ldg(&X2[c0 * 32 + lane]);
        hv.x += w0 * x0.x; hv.y += w0 * x0.y;
    }

    // dense [1,64]@[64,40] + bias
    float acc0 = 0.f, acc1 = 0.f;
    int l8 = 32 + (lane & 7);
#pragma unroll
    for (int k = 0; k < NH; k++) {
        float hk = __shfl_sync(0xffffffffu, (k & 1) ? hv.y : hv.x, k >> 1);
        acc0 += hk * W2s[k * NC + lane];   // cols 0..31
        acc1 += hk * W2s[k * NC + l8];     // cols 32..39 (lanes 0..7)
    }
    float v0 = acc0 + b2s[lane];
    float v1 = acc1 + b2s[l8];
    bool has1 = (lane < 8);

    // log_softmax over 40 classes
    float m = fmaxf(v0, has1 ? v1 : -INFINITY);
#pragma unroll
    for (int o = 16; o > 0; o >>= 1) m = fmaxf(m, __shfl_xor_sync(0xffffffffu, m, o));
    float sum = expf(v0 - m) + (has1 ? expf(v1 - m) : 0.f);
#pragma unroll
    for (int o = 16; o > 0; o >>= 1) sum += __shfl_xor_sync(0xffffffffu, sum, o);
    float lse = m + logf(sum);

    out[r * NC + lane] = v0 - lse;
    if (has1) out[r * NC + 32 + lane] = v1 - lse;
}

// ---------------- launch ----------------
extern "C" void kernel_launch(void* const* d_in, const int* in_sizes, int n_in,
                              void* d_out, int out_size) {
    const float* x    = (const float*)d_in[0];
    const float* M    = (const float*)d_in[1];
    const float* AM   = (const float*)d_in[2];
    const float* adj  = (const float*)d_in[3];
    const float* adjZ = (const float*)d_in[4];
    const float* W0   = (const float*)d_in[5];
    const float* b0   = (const float*)d_in[6];
    const float* W1   = (const float*)d_in[7];
    const float* b1   = (const float*)d_in[8];
    const float* W2   = (const float*)d_in[9];
    const float* b2   = (const float*)d_in[10];
    const int*   row  = (const int*)d_in[11];
    const int*   col  = (const int*)d_in[12];
    float* out = (float*)d_out;

    void *pA, *pH0, *pH1, *pHist;
    cudaGetSymbolAddress(&pA,  g_A);
    cudaGetSymbolAddress(&pH0, g_H0);
    cudaGetSymbolAddress(&pH1, g_H1);
    cudaGetSymbolAddress(&pHist, g_hist);
    float* A  = (float*)pA;
    float* H0 = (float*)pH0;
    float* H1 = (float*)pH1;

    // CSR build (per launch; graph-replay safe)
    cudaMemsetAsync(pHist, 0, NN * sizeof(int));
    hist_kernel<<<(EE + 255) / 256, 256>>>(row);
    scan_kernel<<<1, 1024>>>();
    scatter_kernel<<<(EE + 255) / 256, 256>>>(row, col, adj, adjZ, M);

    const int spmmBlocks = (NN + 7) / 8;          // 8 warps/block, 1 warp/row
    const int gemmBlocks = (NN + 63) / 64;        // BM=64

    // layer 0: h = relu((spmm(adjZ, M*x) * AM) @ W0 + b0)
    spmm128_kernel<<<spmmBlocks, 256>>>(x, AM, A);
    gemm_bias_relu<128, 128, 8><<<gemmBlocks, 256>>>(A, W0, b0, H0);

    // layer 1: h = relu((spmm(adjZ, M*h) * AM) @ W1 + b1)
    spmm128_kernel<<<spmmBlocks, 256>>>(H0, AM, A);
    gemm_bias_relu<128, 64, 4><<<gemmBlocks, 256>>>(A, W1, b1, H1);

    // layer 2: log_softmax(spmm(adj, h) @ W2 + b2)  — fully fused
    spmm64_final_kernel<<<spmmBlocks, 256>>>(H1, W2, b2, out);
}

// round 5
// speedup vs baseline: 1.0555x; 1.0265x over previous
#include <cuda_runtime.h>
#include <math.h>

#define NN 50000
#define EE 800000
#define NF 128
#define NH 64
#define NC 40

// ---- scratch (static device globals; no allocation in kernel_launch) ----
struct __align__(16) Edge { int col; float vZ; float v; float pad; };

__device__ float g_A[NN * NF];    // spmm0 out; later reused as G1 = H0@W1 (50K x 64)
__device__ float g_H0[NN * NF];   // relu(A@W0+b0); later reused as G2 = H1@W2 (50K x 40)
__device__ int   g_hist[NN];
__device__ int   g_rowptr[NN + 1];
__device__ int   g_cursor[NN];
__device__ Edge  g_edges[EE];     // row-sorted edge records (16B packed)

// ---------------- CSR build ----------------
__global__ void hist_kernel(const int* __restrict__ row) {
    int e = blockIdx.x * blockDim.x + threadIdx.x;
    if (e < EE) atomicAdd(&g_hist[row[e]], 1);
}

__global__ void scan_kernel() {
    __shared__ int ssum[1024];
    const int CH = (NN + 1023) / 1024;   // 49
    int t = threadIdx.x;
    int base = t * CH;
    int local = 0;
    for (int i = 0; i < CH; i++) {
        int idx = base + i;
        if (idx < NN) local += g_hist[idx];
    }
    ssum[t] = local;
    __syncthreads();
    for (int off = 1; off < 1024; off <<= 1) {
        int v = (t >= off) ? ssum[t - off] : 0;
        __syncthreads();
        ssum[t] += v;
        __syncthreads();
    }
    int run = ssum[t] - local;
    for (int i = 0; i < CH; i++) {
        int idx = base + i;
        if (idx < NN) {
            g_rowptr[idx] = run;
            g_cursor[idx] = run;
            run += g_hist[idx];
        }
    }
    if (t == 0) g_rowptr[NN] = EE;
}

__global__ void scatter_kernel(const int* __restrict__ row, const int* __restrict__ col,
                               const float* __restrict__ adj, const float* __restrict__ adjZ,
                               const float* __restrict__ M) {
    int e = blockIdx.x * blockDim.x + threadIdx.x;
    if (e >= EE) return;
    int c = col[e];
    int pos = atomicAdd(&g_cursor[row[e]], 1);
    float4 ed;
    ed.x = __int_as_float(c);
    ed.y = adjZ[e] * M[c];   // fold M[col] once for both PaGConv layers
    ed.z = adj[e];
    ed.w = 0.f;
    *(float4*)&g_edges[pos] = ed;
}

// ---------------- SPMM 128-feat (layer 0): one warp per row, xAM epilogue ----------------
__global__ void spmm128_kernel(const float* __restrict__ X, const float* __restrict__ AM,
                               float* __restrict__ out) {
    int r = (blockIdx.x * blockDim.x + threadIdx.x) >> 5;
    if (r >= NN) return;
    int lane = threadIdx.x & 31;
    int s = g_rowptr[r];
    int e = g_rowptr[r + 1];
    const float4* X4 = (const float4*)X;

    float4 acc = make_float4(0.f, 0.f, 0.f, 0.f);
    int i = s;
    for (; i + 4 <= e; i += 4) {
        float4 e0 = __ldg((const float4*)&g_edges[i]);
        float4 e1 = __ldg((const float4*)&g_edges[i + 1]);
        float4 e2 = __ldg((const float4*)&g_edges[i + 2]);
        float4 e3 = __ldg((const float4*)&g_edges[i + 3]);
        float4 x0 = __ldg(&X4[__float_as_int(e0.x) * 32 + lane]);
        float4 x1 = __ldg(&X4[__float_as_int(e1.x) * 32 + lane]);
        float4 x2 = __ldg(&X4[__float_as_int(e2.x) * 32 + lane]);
        float4 x3 = __ldg(&X4[__float_as_int(e3.x) * 32 + lane]);
        acc.x += e0.y * x0.x; acc.y += e0.y * x0.y; acc.z += e0.y * x0.z; acc.w += e0.y * x0.w;
        acc.x += e1.y * x1.x; acc.y += e1.y * x1.y; acc.z += e1.y * x1.z; acc.w += e1.y * x1.w;
        acc.x += e2.y * x2.x; acc.y += e2.y * x2.y; acc.z += e2.y * x2.z; acc.w += e2.y * x2.w;
        acc.x += e3.y * x3.x; acc.y += e3.y * x3.y; acc.z += e3.y * x3.z; acc.w += e3.y * x3.w;
    }
    for (; i < e; i++) {
        float4 e0 = __ldg((const float4*)&g_edges[i]);
        float4 x0 = __ldg(&X4[__float_as_int(e0.x) * 32 + lane]);
        acc.x += e0.y * x0.x; acc.y += e0.y * x0.y; acc.z += e0.y * x0.z; acc.w += e0.y * x0.w;
    }
    float am = __ldg(&AM[r]);
    acc.x *= am; acc.y *= am; acc.z *= am; acc.w *= am;
    ((float4*)out)[r * 32 + lane] = acc;
}

// ---------------- register-tiled fp32 GEMM, optional bias+relu epilogue ----------------
template <int KIN, int NOUT, int TM, bool EPI>
__global__ void gemm_kernel(const float* __restrict__ A,
                            const float* __restrict__ W, const float* __restrict__ bias,
                            float* __restrict__ out) {
    constexpr int TN  = 4;
    constexpr int BK  = 16;
    constexpr int NCT = NOUT / TN;
    constexpr int NRT = 256 / NCT;
    constexpr int BM  = NRT * TM;    // 64

    __shared__ __align__(16) float As[BM][BK];
    __shared__ __align__(16) float Ws[BK][NOUT];

    int tid  = threadIdx.x;
    int ct   = tid % NCT;
    int rt   = tid / NCT;
    int col0 = ct * TN;
    int row0 = rt * TM;
    int br   = blockIdx.x * BM;

    float acc[TM][TN];
#pragma unroll
    for (int i = 0; i < TM; i++)
#pragma unroll
        for (int j = 0; j < TN; j++) acc[i][j] = 0.f;

    for (int kk = 0; kk < KIN; kk += BK) {
        {   // A tile (BM x BK): one float4 per thread
            int m  = tid / (BK / 4);
            int k4 = (tid % (BK / 4)) * 4;
            int gr = br + m;
            float4 v = make_float4(0.f, 0.f, 0.f, 0.f);
            if (gr < NN) v = *(const float4*)&A[gr * KIN + kk + k4];
            *(float4*)&As[m][k4] = v;
        }
#pragma unroll
        for (int i = tid; i < BK * NOUT / 4; i += 256) {
            int k  = i / (NOUT / 4);
            int n4 = (i % (NOUT / 4)) * 4;
            *(float4*)&Ws[k][n4] = *(const float4*)&W[(kk + k) * NOUT + n4];
        }
        __syncthreads();

#pragma unroll
        for (int k = 0; k < BK; k++) {
            float4 w4 = *(const float4*)&Ws[k][col0];
            float a[TM];
#pragma unroll
            for (int i = 0; i < TM; i++) a[i] = As[row0 + i][k];
#pragma unroll
            for (int i = 0; i < TM; i++) {
                acc[i][0] += a[i] * w4.x;
                acc[i][1] += a[i] * w4.y;
                acc[i][2] += a[i] * w4.z;
                acc[i][3] += a[i] * w4.w;
            }
        }
        __syncthreads();
    }

#pragma unroll
    for (int i = 0; i < TM; i++) {
        int gr = br + row0 + i;
        if (gr < NN) {
            float4 o;
            if (EPI) {
                o.x = fmaxf(acc[i][0] + bias[col0 + 0], 0.f);
                o.y = fmaxf(acc[i][1] + bias[col0 + 1], 0.f);
                o.z = fmaxf(acc[i][2] + bias[col0 + 2], 0.f);
                o.w = fmaxf(acc[i][3] + bias[col0 + 3], 0.f);
            } else {
                o = make_float4(acc[i][0], acc[i][1], acc[i][2], acc[i][3]);
            }
            *(float4*)&out[gr * NOUT + col0] = o;
        }
    }
}

// ---- layer 1 fused: h1 = relu(spmm64(vZ, G1)*AM + b1); G2row = h1 @ W2  (one warp/row) ----
__global__ void spmm64_g2_kernel(const float* __restrict__ G1, const float* __restrict__ AM,
                                 const float* __restrict__ b1, const float* __restrict__ W2,
                                 float* __restrict__ G2) {
    __shared__ float W2s[NH * NC];
    int tid = threadIdx.x;
    for (int i = tid; i < NH * NC; i += blockDim.x) W2s[i] = W2[i];
    __syncthreads();

    int r = blockIdx.x * (blockDim.x >> 5) + (tid >> 5);
    if (r >= NN) return;
    int lane = tid & 31;
    int s = g_rowptr[r];
    int e = g_rowptr[r + 1];
    const float2* X2 = (const float2*)G1;

    float2 acc = make_float2(0.f, 0.f);
    int i = s;
    for (; i + 4 <= e; i += 4) {
        float4 e0 = __ldg((const float4*)&g_edges[i]);
        float4 e1 = __ldg((const float4*)&g_edges[i + 1]);
        float4 e2 = __ldg((const float4*)&g_edges[i + 2]);
        float4 e3 = __ldg((const float4*)&g_edges[i + 3]);
        float2 x0 = __ldg(&X2[__float_as_int(e0.x) * 32 + lane]);
        float2 x1 = __ldg(&X2[__float_as_int(e1.x) * 32 + lane]);
        float2 x2 = __ldg(&X2[__float_as_int(e2.x) * 32 + lane]);
        float2 x3 = __ldg(&X2[__float_as_int(e3.x) * 32 + lane]);
        acc.x += e0.y * x0.x; acc.y += e0.y * x0.y;
        acc.x += e1.y * x1.x; acc.y += e1.y * x1.y;
        acc.x += e2.y * x2.x; acc.y += e2.y * x2.y;
        acc.x += e3.y * x3.x; acc.y += e3.y * x3.y;
    }
    for (; i < e; i++) {
        float4 e0 = __ldg((const float4*)&g_edges[i]);
        float2 x0 = __ldg(&X2[__float_as_int(e0.x) * 32 + lane]);
        acc.x += e0.y * x0.x; acc.y += e0.y * x0.y;
    }

    // epilogue: h1 = relu(acc*AM + b1)  (float2 per lane = h[2l], h[2l+1])
    float am = __ldg(&AM[r]);
    float2 b = __ldg(&((const float2*)b1)[lane]);
    float2 hv;
    hv.x = fmaxf(acc.x * am + b.x, 0.f);
    hv.y = fmaxf(acc.y * am + b.y, 0.f);

    // G2 row = h1 @ W2   ([1,64]@[64,40])
    float acc0 = 0.f, acc1 = 0.f;
    int l8 = 32 + (lane & 7);
#pragma unroll
    for (int k = 0; k < NH; k++) {
        float hk = __shfl_sync(0xffffffffu, (k & 1) ? hv.y : hv.x, k >> 1);
        acc0 += hk * W2s[k * NC + lane];
        acc1 += hk * W2s[k * NC + l8];
    }
    G2[r * NC + lane] = acc0;
    if (lane < 8) G2[r * NC + 32 + lane] = acc1;
}

// ---- layer 2 fused: out = log_softmax(spmm40(v, G2) + b2), one warp/row ----
__global__ void spmm40_final_kernel(const float* __restrict__ G2, const float* __restrict__ b2,
                                    float* __restrict__ out) {
    int tid = threadIdx.x;
    int r = blockIdx.x * (blockDim.x >> 5) + (tid >> 5);
    if (r >= NN) return;
    int lane = tid & 31;
    bool act = lane < 20;            // 20 lanes x float2 = 40 feats
    int s = g_rowptr[r];
    int e = g_rowptr[r + 1];
    const float2* X2 = (const float2*)G2;

    float2 acc = make_float2(0.f, 0.f);
    int i = s;
    for (; i + 4 <= e; i += 4) {
        float4 e0 = __ldg((const float4*)&g_edges[i]);
        float4 e1 = __ldg((const float4*)&g_edges[i + 1]);
        float4 e2 = __ldg((const float4*)&g_edges[i + 2]);
        float4 e3 = __ldg((const float4*)&g_edges[i + 3]);
        if (act) {
            float2 x0 = __ldg(&X2[__float_as_int(e0.x) * 20 + lane]);
            float2 x1 = __ldg(&X2[__float_as_int(e1.x) * 20 + lane]);
            float2 x2 = __ldg(&X2[__float_as_int(e2.x) * 20 + lane]);
            float2 x3 = __ldg(&X2[__float_as_int(e3.x) * 20 + lane]);
            acc.x += e0.z * x0.x; acc.y += e0.z * x0.y;
            acc.x += e1.z * x1.x; acc.y += e1.z * x1.y;
            acc.x += e2.z * x2.x; acc.y += e2.z * x2.y;
            acc.x += e3.z * x3.x; acc.y += e3.z * x3.y;
        }
    }
    for (; i < e; i++) {
        float4 e0 = __ldg((const float4*)&g_edges[i]);
        if (act) {
            float2 x0 = __ldg(&X2[__float_as_int(e0.x) * 20 + lane]);
            acc.x += e0.z * x0.x; acc.y += e0.z * x0.y;
        }
    }

    float v0 = 0.f, v1 = 0.f;
    if (act) {
        float2 b = __ldg(&((const float2*)b2)[lane]);
        v0 = acc.x + b.x;
        v1 = acc.y + b.y;
    }

    float m = act ? fmaxf(v0, v1) : -INFINITY;
#pragma unroll
    for (int o = 16; o > 0; o >>= 1) m = fmaxf(m, __shfl_xor_sync(0xffffffffu, m, o));
    float sum = act ? (expf(v0 - m) + expf(v1 - m)) : 0.f;
#pragma unroll
    for (int o = 16; o > 0; o >>= 1) sum += __shfl_xor_sync(0xffffffffu, sum, o);
    float lse = m + logf(sum);

    if (act) {
        float2 o2 = make_float2(v0 - lse, v1 - lse);
        ((float2*)out)[r * 20 + lane] = o2;
    }
}

// ---------------- launch ----------------
extern "C" void kernel_launch(void* const* d_in, const int* in_sizes, int n_in,
                              void* d_out, int out_size) {
    const float* x    = (const float*)d_in[0];
    const float* M    = (const float*)d_in[1];
    const float* AM   = (const float*)d_in[2];
    const float* adj  = (const float*)d_in[3];
    const float* adjZ = (const float*)d_in[4];
    const float* W0   = (const float*)d_in[5];
    const float* b0   = (const float*)d_in[6];
    const float* W1   = (const float*)d_in[7];
    const float* b1   = (const float*)d_in[8];
    const float* W2   = (const float*)d_in[9];
    const float* b2   = (const float*)d_in[10];
    const int*   row  = (const int*)d_in[11];
    const int*   col  = (const int*)d_in[12];
    float* out = (float*)d_out;

    void *pA, *pH0, *pHist;
    cudaGetSymbolAddress(&pA,  g_A);
    cudaGetSymbolAddress(&pH0, g_H0);
    cudaGetSymbolAddress(&pHist, g_hist);
    float* A  = (float*)pA;    // spmm0 out, then reused as G1 (50K x 64)
    float* H0 = (float*)pH0;   // relu out, then reused as G2 (50K x 40)

    // CSR build
    cudaMemsetAsync(pHist, 0, NN * sizeof(int));
    hist_kernel<<<(EE + 255) / 256, 256>>>(row);
    scan_kernel<<<1, 1024>>>();
    scatter_kernel<<<(EE + 255) / 256, 256>>>(row, col, adj, adjZ, M);

    const int spmmBlocks = (NN + 7) / 8;      // 8 warps/block, 1 warp/row
    const int gemmBlocks = (NN + 63) / 64;    // BM=64

    // layer 0: H0 = relu((spmm(adjZ, M*x) * AM) @ W0 + b0)
    spmm128_kernel<<<spmmBlocks, 256>>>(x, AM, A);
    gemm_kernel<128, 128, 8, true><<<gemmBlocks, 256>>>(A, W0, b0, H0);

    // layer 1 (commuted): G1 = H0 @ W1 (128->64), then
    //   G2row = relu(spmm64(vZ, G1)*AM + b1) @ W2   (fused, 64->40)
    gemm_kernel<128, 64, 4, false><<<gemmBlocks, 256>>>(H0, W1, nullptr, A);   // A := G1
    spmm64_g2_kernel<<<spmmBlocks, 256>>>(A, AM, b1, W2, H0);                  // H0 := G2

    // layer 2 (commuted): out = log_softmax(spmm40(adj, G2) + b2)
    spmm40_final_kernel<<<spmmBlocks, 256>>>(H0, b2, out);
}

// round 6
// speedup vs baseline: 1.0779x; 1.0212x over previous
#include <cuda_runtime.h>
#include <cuda_fp16.h>
#include <math.h>

#define NN 50000
#define EE 800000
#define NF 128
#define NH 64
#define NC 40

// ---- scratch (static device globals; no allocation in kernel_launch) ----
__device__ __half  g_xh[NN * NF];    // fp16 copy of x
__device__ float   g_Af[NN * NF];    // spmm0 output (fp32)
__device__ float   g_H0[NN * NF];    // relu(A@W0+b0) (fp32)
__device__ __half  g_G1h[NN * NH];   // H0@W1 in fp16 (gathered by spmm64)
__device__ __half  g_G2h[NN * NC];   // h1@W2 in fp16 (gathered by spmm40)
__device__ int     g_hist[NN];
__device__ int     g_rowptr[NN + 1];
__device__ int     g_cursor[NN];
__device__ float2  g_eZ[EE];         // {col_as_float, adjZ*M[col]}  (layers 0,1)
__device__ float2  g_eV[EE];         // {col_as_float, adj}          (layer 2)

// ---- f32x2 packed helpers (sm_103a FFMA2 path; ptxas won't auto-fuse) ----
__device__ __forceinline__ unsigned long long pack2(float a, float b) {
    unsigned long long d;
    asm("mov.b64 %0, {%1, %2};" : "=l"(d) : "r"(__float_as_uint(a)), "r"(__float_as_uint(b)));
    return d;
}
__device__ __forceinline__ void fma2(unsigned long long& d, unsigned long long a, unsigned long long b) {
    asm("fma.rn.f32x2 %0, %1, %2, %0;" : "+l"(d) : "l"(a), "l"(b));
}
__device__ __forceinline__ float2 unpack2(unsigned long long v) {
    unsigned int lo, hi;
    asm("mov.b64 {%0, %1}, %2;" : "=r"(lo), "=r"(hi) : "l"(v));
    return make_float2(__uint_as_float(lo), __uint_as_float(hi));
}

// ---------------- CSR build ----------------
__global__ void hist_kernel(const int* __restrict__ row) {
    int e = blockIdx.x * blockDim.x + threadIdx.x;
    if (e < EE) atomicAdd(&g_hist[row[e]], 1);
}

__global__ void scan_kernel() {
    __shared__ int ssum[1024];
    const int CH = (NN + 1023) / 1024;   // 49
    int t = threadIdx.x;
    int base = t * CH;
    int local = 0;
    for (int i = 0; i < CH; i++) {
        int idx = base + i;
        if (idx < NN) local += g_hist[idx];
    }
    ssum[t] = local;
    __syncthreads();
    for (int off = 1; off < 1024; off <<= 1) {
        int v = (t >= off) ? ssum[t - off] : 0;
        __syncthreads();
        ssum[t] += v;
        __syncthreads();
    }
    int run = ssum[t] - local;
    for (int i = 0; i < CH; i++) {
        int idx = base + i;
        if (idx < NN) {
            g_rowptr[idx] = run;
            g_cursor[idx] = run;
            run += g_hist[idx];
        }
    }
    if (t == 0) g_rowptr[NN] = EE;
}

__global__ void scatter_kernel(const int* __restrict__ row, const int* __restrict__ col,
                               const float* __restrict__ adj, const float* __restrict__ adjZ,
                               const float* __restrict__ M) {
    int e = blockIdx.x * blockDim.x + threadIdx.x;
    if (e >= EE) return;
    int c = col[e];
    int pos = atomicAdd(&g_cursor[row[e]], 1);
    g_eZ[pos] = make_float2(__int_as_float(c), adjZ[e] * M[c]);
    g_eV[pos] = make_float2(__int_as_float(c), adj[e]);
}

// ---------------- fp32 -> fp16 convert ----------------
__global__ void tohalf_kernel(const float* __restrict__ in, __half2* __restrict__ out, int n2) {
    int i = blockIdx.x * blockDim.x + threadIdx.x;
    if (i < n2) {
        float2 v = ((const float2*)in)[i];
        out[i] = __float22half2_rn(v);
    }
}

// ---------------- SPMM 128-feat (layer 0), fp16 gathers, fp32 accum ----------------
__global__ void spmm128h_kernel(const __half* __restrict__ Xh, const float* __restrict__ AM,
                                float* __restrict__ out) {
    int r = (blockIdx.x * blockDim.x + threadIdx.x) >> 5;
    if (r >= NN) return;
    int lane = threadIdx.x & 31;
    int s = g_rowptr[r];
    int e = g_rowptr[r + 1];
    const uint2* X = (const uint2*)Xh;   // 4 halves per 8B, 32 uint2 per row

    float4 acc = make_float4(0.f, 0.f, 0.f, 0.f);
    int i = s;
    for (; i + 4 <= e; i += 4) {
        float2 e0 = __ldg(&g_eZ[i]);
        float2 e1 = __ldg(&g_eZ[i + 1]);
        float2 e2 = __ldg(&g_eZ[i + 2]);
        float2 e3 = __ldg(&g_eZ[i + 3]);
        uint2 u0 = __ldg(&X[__float_as_int(e0.x) * 32 + lane]);
        uint2 u1 = __ldg(&X[__float_as_int(e1.x) * 32 + lane]);
        uint2 u2 = __ldg(&X[__float_as_int(e2.x) * 32 + lane]);
        uint2 u3 = __ldg(&X[__float_as_int(e3.x) * 32 + lane]);
        float2 a0 = __half22float2(*(__half2*)&u0.x), b0 = __half22float2(*(__half2*)&u0.y);
        float2 a1 = __half22float2(*(__half2*)&u1.x), b1 = __half22float2(*(__half2*)&u1.y);
        float2 a2 = __half22float2(*(__half2*)&u2.x), b2 = __half22float2(*(__half2*)&u2.y);
        float2 a3 = __half22float2(*(__half2*)&u3.x), b3 = __half22float2(*(__half2*)&u3.y);
        acc.x += e0.y * a0.x; acc.y += e0.y * a0.y; acc.z += e0.y * b0.x; acc.w += e0.y * b0.y;
        acc.x += e1.y * a1.x; acc.y += e1.y * a1.y; acc.z += e1.y * b1.x; acc.w += e1.y * b1.y;
        acc.x += e2.y * a2.x; acc.y += e2.y * a2.y; acc.z += e2.y * b2.x; acc.w += e2.y * b2.y;
        acc.x += e3.y * a3.x; acc.y += e3.y * a3.y; acc.z += e3.y * b3.x; acc.w += e3.y * b3.y;
    }
    for (; i < e; i++) {
        float2 e0 = __ldg(&g_eZ[i]);
        uint2 u0 = __ldg(&X[__float_as_int(e0.x) * 32 + lane]);
        float2 a0 = __half22float2(*(__half2*)&u0.x), b0 = __half22float2(*(__half2*)&u0.y);
        acc.x += e0.y * a0.x; acc.y += e0.y * a0.y; acc.z += e0.y * b0.x; acc.w += e0.y * b0.y;
    }
    float am = __ldg(&AM[r]);
    acc.x *= am; acc.y *= am; acc.z *= am; acc.w *= am;
    ((float4*)out)[r * 32 + lane] = acc;
}

// ---------------- register-tiled GEMM with f32x2 FMA ----------------
// EPI 0: plain fp32 out; 1: bias+relu fp32 out; 2: fp16 out (no bias)
template <int KIN, int NOUT, int TM, int EPI>
__global__ void gemm_kernel(const float* __restrict__ A,
                            const float* __restrict__ W, const float* __restrict__ bias,
                            void* __restrict__ out_) {
    constexpr int TN  = 4;
    constexpr int BK  = 16;
    constexpr int NCT = NOUT / TN;
    constexpr int NRT = 256 / NCT;
    constexpr int BM  = NRT * TM;    // 64

    __shared__ __align__(16) float As[BM][BK];
    __shared__ __align__(16) float Ws[BK][NOUT];

    int tid  = threadIdx.x;
    int ct   = tid % NCT;
    int rt   = tid / NCT;
    int col0 = ct * TN;
    int row0 = rt * TM;
    int br   = blockIdx.x * BM;

    unsigned long long acc0[TM], acc1[TM];   // (c0,c1), (c2,c3) packed f32x2
#pragma unroll
    for (int i = 0; i < TM; i++) { acc0[i] = 0ull; acc1[i] = 0ull; }

    for (int kk = 0; kk < KIN; kk += BK) {
        {   // A tile (BM x BK): one float4 per thread
            int m  = tid / (BK / 4);
            int k4 = (tid % (BK / 4)) * 4;
            int gr = br + m;
            float4 v = make_float4(0.f, 0.f, 0.f, 0.f);
            if (gr < NN) v = *(const float4*)&A[gr * KIN + kk + k4];
            *(float4*)&As[m][k4] = v;
        }
#pragma unroll
        for (int i = tid; i < BK * NOUT / 4; i += 256) {
            int k  = i / (NOUT / 4);
            int n4 = (i % (NOUT / 4)) * 4;
            *(float4*)&Ws[k][n4] = *(const float4*)&W[(kk + k) * NOUT + n4];
        }
        __syncthreads();

#pragma unroll
        for (int k = 0; k < BK; k++) {
            float4 w4 = *(const float4*)&Ws[k][col0];
            unsigned long long wp0 = pack2(w4.x, w4.y);
            unsigned long long wp1 = pack2(w4.z, w4.w);
#pragma unroll
            for (int i = 0; i < TM; i++) {
                float a = As[row0 + i][k];
                unsigned long long ap = pack2(a, a);
                fma2(acc0[i], ap, wp0);
                fma2(acc1[i], ap, wp1);
            }
        }
        __syncthreads();
    }

#pragma unroll
    for (int i = 0; i < TM; i++) {
        int gr = br + row0 + i;
        if (gr >= NN) continue;
        float2 c01 = unpack2(acc0[i]);
        float2 c23 = unpack2(acc1[i]);
        if (EPI == 1) {
            float4 o;
            o.x = fmaxf(c01.x + bias[col0 + 0], 0.f);
            o.y = fmaxf(c01.y + bias[col0 + 1], 0.f);
            o.z = fmaxf(c23.x + bias[col0 + 2], 0.f);
            o.w = fmaxf(c23.y + bias[col0 + 3], 0.f);
            *(float4*)&((float*)out_)[gr * NOUT + col0] = o;
        } else if (EPI == 2) {
            __half2 h0 = __float22half2_rn(c01);
            __half2 h1 = __float22half2_rn(c23);
            uint2 u = make_uint2(*(unsigned*)&h0, *(unsigned*)&h1);
            *(uint2*)&((__half*)out_)[gr * NOUT + col0] = u;
        } else {
            float4 o = make_float4(c01.x, c01.y, c23.x, c23.y);
            *(float4*)&((float*)out_)[gr * NOUT + col0] = o;
        }
    }
}

// ---- layer 1 fused: h1 = relu(spmm64(vZ, G1h)*AM + b1); G2h row = h1 @ W2 ----
__global__ void spmm64_g2_kernel(const __half* __restrict__ G1h, const float* __restrict__ AM,
                                 const float* __restrict__ b1, const float* __restrict__ W2,
                                 __half* __restrict__ G2h) {
    __shared__ float W2s[NH * NC];
    int tid = threadIdx.x;
    for (int i = tid; i < NH * NC; i += blockDim.x) W2s[i] = W2[i];
    __syncthreads();

    int r = blockIdx.x * (blockDim.x >> 5) + (tid >> 5);
    if (r >= NN) return;
    int lane = tid & 31;
    int s = g_rowptr[r];
    int e = g_rowptr[r + 1];
    const __half2* X = (const __half2*)G1h;   // 32 half2 per row

    float2 acc = make_float2(0.f, 0.f);
    int i = s;
    for (; i + 4 <= e; i += 4) {
        float2 e0 = __ldg(&g_eZ[i]);
        float2 e1 = __ldg(&g_eZ[i + 1]);
        float2 e2 = __ldg(&g_eZ[i + 2]);
        float2 e3 = __ldg(&g_eZ[i + 3]);
        float2 x0 = __half22float2(__ldg(&X[__float_as_int(e0.x) * 32 + lane]));
        float2 x1 = __half22float2(__ldg(&X[__float_as_int(e1.x) * 32 + lane]));
        float2 x2 = __half22float2(__ldg(&X[__float_as_int(e2.x) * 32 + lane]));
        float2 x3 = __half22float2(__ldg(&X[__float_as_int(e3.x) * 32 + lane]));
        acc.x += e0.y * x0.x; acc.y += e0.y * x0.y;
        acc.x += e1.y * x1.x; acc.y += e1.y * x1.y;
        acc.x += e2.y * x2.x; acc.y += e2.y * x2.y;
        acc.x += e3.y * x3.x; acc.y += e3.y * x3.y;
    }
    for (; i < e; i++) {
        float2 e0 = __ldg(&g_eZ[i]);
        float2 x0 = __half22float2(__ldg(&X[__float_as_int(e0.x) * 32 + lane]));
        acc.x += e0.y * x0.x; acc.y += e0.y * x0.y;
    }

    float am = __ldg(&AM[r]);
    float2 b = __ldg(&((const float2*)b1)[lane]);
    float2 hv;
    hv.x = fmaxf(acc.x * am + b.x, 0.f);
    hv.y = fmaxf(acc.y * am + b.y, 0.f);

    // G2 row = h1 @ W2   ([1,64]@[64,40])
    float acc0 = 0.f, acc1 = 0.f;
    int l8 = 32 + (lane & 7);
#pragma unroll
    for (int k = 0; k < NH; k++) {
        float hk = __shfl_sync(0xffffffffu, (k & 1) ? hv.y : hv.x, k >> 1);
        acc0 += hk * W2s[k * NC + lane];   // cols 0..31 (lane = col)
        acc1 += hk * W2s[k * NC + l8];     // cols 32..39 (valid on lanes 0..7)
    }

    // pack to half2 pairs: lanes 0..15 -> cols (2l,2l+1); lanes 16..19 -> cols (32+2(l-16), +1)
    int src0 = (lane < 16) ? (2 * lane) : (2 * (lane - 16));
    float p0 = __shfl_sync(0xffffffffu, acc0, src0);
    float p1 = __shfl_sync(0xffffffffu, acc0, src0 + 1);
    float q0 = __shfl_sync(0xffffffffu, acc1, src0);
    float q1 = __shfl_sync(0xffffffffu, acc1, src0 + 1);
    if (lane < 16) {
        ((__half2*)G2h)[r * 20 + lane] = __float22half2_rn(make_float2(p0, p1));
    } else if (lane < 20) {
        ((__half2*)G2h)[r * 20 + lane] = __float22half2_rn(make_float2(q0, q1));
    }
}

// ---- layer 2 fused: out = log_softmax(spmm40(v, G2h) + b2), one warp/row ----
__global__ void spmm40_final_kernel(const __half* __restrict__ G2h, const float* __restrict__ b2,
                                    float* __restrict__ out) {
    int tid = threadIdx.x;
    int r = blockIdx.x * (blockDim.x >> 5) + (tid >> 5);
    if (r >= NN) return;
    int lane = tid & 31;
    bool act = lane < 20;            // 20 lanes x half2 = 40 feats
    int s = g_rowptr[r];
    int e = g_rowptr[r + 1];
    const __half2* X = (const __half2*)G2h;
    int li = act ? lane : 0;

    float2 acc = make_float2(0.f, 0.f);
    int i = s;
    for (; i + 4 <= e; i += 4) {
        float2 e0 = __ldg(&g_eV[i]);
        float2 e1 = __ldg(&g_eV[i + 1]);
        float2 e2 = __ldg(&g_eV[i + 2]);
        float2 e3 = __ldg(&g_eV[i + 3]);
        float2 x0 = __half22float2(__ldg(&X[__float_as_int(e0.x) * 20 + li]));
        float2 x1 = __half22float2(__ldg(&X[__float_as_int(e1.x) * 20 + li]));
        float2 x2 = __half22float2(__ldg(&X[__float_as_int(e2.x) * 20 + li]));
        float2 x3 = __half22float2(__ldg(&X[__float_as_int(e3.x) * 20 + li]));
        acc.x += e0.y * x0.x; acc.y += e0.y * x0.y;
        acc.x += e1.y * x1.x; acc.y += e1.y * x1.y;
        acc.x += e2.y * x2.x; acc.y += e2.y * x2.y;
        acc.x += e3.y * x3.x; acc.y += e3.y * x3.y;
    }
    for (; i < e; i++) {
        float2 e0 = __ldg(&g_eV[i]);
        float2 x0 = __half22float2(__ldg(&X[__float_as_int(e0.x) * 20 + li]));
        acc.x += e0.y * x0.x; acc.y += e0.y * x0.y;
    }

    float v0 = 0.f, v1 = 0.f;
    if (act) {
        float2 b = __ldg(&((const float2*)b2)[lane]);
        v0 = acc.x + b.x;
        v1 = acc.y + b.y;
    }

    float m = act ? fmaxf(v0, v1) : -INFINITY;
#pragma unroll
    for (int o = 16; o > 0; o >>= 1) m = fmaxf(m, __shfl_xor_sync(0xffffffffu, m, o));
    float sum = act ? (expf(v0 - m) + expf(v1 - m)) : 0.f;
#pragma unroll
    for (int o = 16; o > 0; o >>= 1) sum += __shfl_xor_sync(0xffffffffu, sum, o);
    float lse = m + logf(sum);

    if (act) {
        ((float2*)out)[r * 20 + lane] = make_float2(v0 - lse, v1 - lse);
    }
}

// ---------------- launch ----------------
extern "C" void kernel_launch(void* const* d_in, const int* in_sizes, int n_in,
                              void* d_out, int out_size) {
    const float* x    = (const float*)d_in[0];
    const float* M    = (const float*)d_in[1];
    const float* AM   = (const float*)d_in[2];
    const float* adj  = (const float*)d_in[3];
    const float* adjZ = (const float*)d_in[4];
    const float* W0   = (const float*)d_in[5];
    const float* b0   = (const float*)d_in[6];
    const float* W1   = (const float*)d_in[7];
    const float* b1   = (const float*)d_in[8];
    const float* W2   = (const float*)d_in[9];
    const float* b2   = (const float*)d_in[10];
    const int*   row  = (const int*)d_in[11];
    const int*   col  = (const int*)d_in[12];
    float* out = (float*)d_out;

    void *pXh, *pAf, *pH0, *pG1h, *pG2h, *pHist;
    cudaGetSymbolAddress(&pXh,  g_xh);
    cudaGetSymbolAddress(&pAf,  g_Af);
    cudaGetSymbolAddress(&pH0,  g_H0);
    cudaGetSymbolAddress(&pG1h, g_G1h);
    cudaGetSymbolAddress(&pG2h, g_G2h);
    cudaGetSymbolAddress(&pHist, g_hist);

    // CSR build + x conversion
    cudaMemsetAsync(pHist, 0, NN * sizeof(int));
    hist_kernel<<<(EE + 255) / 256, 256>>>(row);
    tohalf_kernel<<<(NN * NF / 2 + 255) / 256, 256>>>(x, (__half2*)pXh, NN * NF / 2);
    scan_kernel<<<1, 1024>>>();
    scatter_kernel<<<(EE + 255) / 256, 256>>>(row, col, adj, adjZ, M);

    const int spmmBlocks = (NN + 7) / 8;      // 8 warps/block, 1 warp/row
    const int gemmBlocks = (NN + 63) / 64;    // BM=64

    // layer 0: H0 = relu((spmm(adjZ, M*x) * AM) @ W0 + b0)
    spmm128h_kernel<<<spmmBlocks, 256>>>((const __half*)pXh, AM, (float*)pAf);
    gemm_kernel<128, 128, 8, 1><<<gemmBlocks, 256>>>((const float*)pAf, W0, b0, pH0);

    // layer 1 (commuted): G1h = H0 @ W1 (128->64, fp16 out), then
    //   G2h row = relu(spmm64(vZ, G1h)*AM + b1) @ W2   (fused, 64->40, fp16 out)
    gemm_kernel<128, 64, 4, 2><<<gemmBlocks, 256>>>((const float*)pH0, W1, nullptr, pG1h);
    spmm64_g2_kernel<<<spmmBlocks, 256>>>((const __half*)pG1h, AM, b1, W2, (__half*)pG2h);

    // layer 2 (commuted): out = log_softmax(spmm40(adj, G2h) + b2)
    spmm40_final_kernel<<<spmmBlocks, 256>>>((const __half*)pG2h, b2, out);
}

// round 7
// speedup vs baseline: 1.2174x; 1.1294x over previous
#include <cuda_runtime.h>
#include <cuda_fp16.h>
#include <math.h>

#define NN 50000
#define EE 800000
#define NF 128
#define NH 64
#define NC 40

// ---- scratch (static device globals; no allocation in kernel_launch) ----
__device__ __half  g_xh[NN * NF];    // fp16 copy of x
__device__ float   g_Af[NN * NF];    // spmm0 output (fp32)
__device__ float   g_H0[NN * NF];    // relu(A@W0+b0) (fp32)
__device__ __half  g_G1h[NN * NH];   // H0@W1 in fp16 (gathered by spmm64)
__device__ __half  g_G2h[NN * NC];   // h1@W2 in fp16 (gathered by spmm40)
__device__ int     g_hist[NN];
__device__ int     g_rowptr[NN + 1];
__device__ int     g_cursor[NN];
__device__ float2  g_eZ[EE];         // {col_as_float, adjZ*M[col]}  (layers 0,1)
__device__ float2  g_eV[EE];         // {col_as_float, adj}          (layer 2)

// ---------------- CSR build ----------------
__global__ void hist_kernel(const int* __restrict__ row) {
    int e = blockIdx.x * blockDim.x + threadIdx.x;
    if (e < EE) atomicAdd(&g_hist[row[e]], 1);
}

__global__ void scan_kernel() {
    __shared__ int ssum[1024];
    const int CH = (NN + 1023) / 1024;   // 49
    int t = threadIdx.x;
    int base = t * CH;
    int local = 0;
    for (int i = 0; i < CH; i++) {
        int idx = base + i;
        if (idx < NN) local += g_hist[idx];
    }
    ssum[t] = local;
    __syncthreads();
    for (int off = 1; off < 1024; off <<= 1) {
        int v = (t >= off) ? ssum[t - off] : 0;
        __syncthreads();
        ssum[t] += v;
        __syncthreads();
    }
    int run = ssum[t] - local;
    for (int i = 0; i < CH; i++) {
        int idx = base + i;
        if (idx < NN) {
            g_rowptr[idx] = run;
            g_cursor[idx] = run;
            run += g_hist[idx];
        }
    }
    if (t == 0) g_rowptr[NN] = EE;
}

__global__ void scatter_kernel(const int* __restrict__ row, const int* __restrict__ col,
                               const float* __restrict__ adj, const float* __restrict__ adjZ,
                               const float* __restrict__ M) {
    int e = blockIdx.x * blockDim.x + threadIdx.x;
    if (e >= EE) return;
    int c = col[e];
    int pos = atomicAdd(&g_cursor[row[e]], 1);
    g_eZ[pos] = make_float2(__int_as_float(c), adjZ[e] * M[c]);
    g_eV[pos] = make_float2(__int_as_float(c), adj[e]);
}

// ---------------- fp32 -> fp16 convert ----------------
__global__ void tohalf_kernel(const float* __restrict__ in, __half2* __restrict__ out, int n2) {
    int i = blockIdx.x * blockDim.x + threadIdx.x;
    if (i < n2) {
        float2 v = ((const float2*)in)[i];
        out[i] = __float22half2_rn(v);
    }
}

// ---------------- SPMM 128-feat (layer 0), fp16 gathers, fp32 accum ----------------
__global__ void spmm128h_kernel(const __half* __restrict__ Xh, const float* __restrict__ AM,
                                float* __restrict__ out) {
    int r = (blockIdx.x * blockDim.x + threadIdx.x) >> 5;
    if (r >= NN) return;
    int lane = threadIdx.x & 31;
    int s = g_rowptr[r];
    int e = g_rowptr[r + 1];
    const uint2* X = (const uint2*)Xh;   // 4 halves per 8B, 32 uint2 per row

    float4 acc = make_float4(0.f, 0.f, 0.f, 0.f);
    int i = s;
    for (; i + 4 <= e; i += 4) {
        float2 e0 = __ldg(&g_eZ[i]);
        float2 e1 = __ldg(&g_eZ[i + 1]);
        float2 e2 = __ldg(&g_eZ[i + 2]);
        float2 e3 = __ldg(&g_eZ[i + 3]);
        uint2 u0 = __ldg(&X[__float_as_int(e0.x) * 32 + lane]);
        uint2 u1 = __ldg(&X[__float_as_int(e1.x) * 32 + lane]);
        uint2 u2 = __ldg(&X[__float_as_int(e2.x) * 32 + lane]);
        uint2 u3 = __ldg(&X[__float_as_int(e3.x) * 32 + lane]);
        float2 a0 = __half22float2(*(__half2*)&u0.x), b0 = __half22float2(*(__half2*)&u0.y);
        float2 a1 = __half22float2(*(__half2*)&u1.x), b1 = __half22float2(*(__half2*)&u1.y);
        float2 a2 = __half22float2(*(__half2*)&u2.x), b2 = __half22float2(*(__half2*)&u2.y);
        float2 a3 = __half22float2(*(__half2*)&u3.x), b3 = __half22float2(*(__half2*)&u3.y);
        acc.x += e0.y * a0.x; acc.y += e0.y * a0.y; acc.z += e0.y * b0.x; acc.w += e0.y * b0.y;
        acc.x += e1.y * a1.x; acc.y += e1.y * a1.y; acc.z += e1.y * b1.x; acc.w += e1.y * b1.y;
        acc.x += e2.y * a2.x; acc.y += e2.y * a2.y; acc.z += e2.y * b2.x; acc.w += e2.y * b2.y;
        acc.x += e3.y * a3.x; acc.y += e3.y * a3.y; acc.z += e3.y * b3.x; acc.w += e3.y * b3.y;
    }
    for (; i < e; i++) {
        float2 e0 = __ldg(&g_eZ[i]);
        uint2 u0 = __ldg(&X[__float_as_int(e0.x) * 32 + lane]);
        float2 a0 = __half22float2(*(__half2*)&u0.x), b0 = __half22float2(*(__half2*)&u0.y);
        acc.x += e0.y * a0.x; acc.y += e0.y * a0.y; acc.z += e0.y * b0.x; acc.w += e0.y * b0.y;
    }
    float am = __ldg(&AM[r]);
    acc.x *= am; acc.y *= am; acc.z *= am; acc.w *= am;
    ((float4*)out)[r * 32 + lane] = acc;
}

// ---------------- tf32 tensor-core GEMM (mma.sync m16n8k8) ----------------
// EPI 1: bias+relu, fp32 out.  EPI 2: fp16 out, no bias.
// Block: 256 thr (8 warps, 4x2 warp grid), BM=128, BN=NOUT, BK=16.
__device__ __forceinline__ unsigned f2tf32(float v) {
    unsigned r;
    asm("cvt.rna.tf32.f32 %0, %1;" : "=r"(r) : "f"(v));
    return r;
}

template <int KIN, int NOUT, int EPI>
__global__ __launch_bounds__(256) void gemm_tf32_kernel(
        const float* __restrict__ A, const float* __restrict__ W,
        const float* __restrict__ bias, void* __restrict__ out_) {
    constexpr int BM = 128;
    constexpr int BK = 16;
    constexpr int AS = 20;          // As row stride (conflict-free a-frag LDS)
    constexpr int WS = NOUT + 8;    // Ws row stride; (NOUT+8) % 32 == 8 -> conflict-free b-frag
    constexpr int WN = NOUT / 2;    // warp tile cols (4x2 warp grid)
    constexpr int MF = 2;           // 32 rows per warp = 2 m-frags
    constexpr int NFR = WN / 8;     // n-frags per warp (8 or 4)

    __shared__ __align__(16) unsigned As[BM * AS];
    __shared__ __align__(16) unsigned Ws[BK * WS];
    __shared__ float biass[NOUT];

    int tid    = threadIdx.x;
    int lane   = tid & 31;
    int wid    = tid >> 5;
    int warp_m = wid & 3;           // 0..3
    int warp_n = wid >> 2;          // 0..1
    int br     = blockIdx.x * BM;

    if (EPI == 1) {
        if (tid < NOUT) biass[tid] = bias[tid];
    }

    float acc[MF][NFR][4];
#pragma unroll
    for (int i = 0; i < MF; i++)
#pragma unroll
        for (int j = 0; j < NFR; j++)
#pragma unroll
            for (int k = 0; k < 4; k++) acc[i][j][k] = 0.f;

    int qr = lane >> 2;       // lane/4
    int qc = lane & 3;        // lane%4

    for (int kk = 0; kk < KIN; kk += BK) {
        // A tile: BM x BK floats -> tf32 in smem. 512 float4, 2 per thread.
#pragma unroll
        for (int it = 0; it < 2; it++) {
            int i  = tid + it * 256;
            int m  = i >> 2;
            int k4 = (i & 3) * 4;
            int gr = br + m;
            float4 v = make_float4(0.f, 0.f, 0.f, 0.f);
            if (gr < NN) v = *(const float4*)&A[gr * KIN + kk + k4];
            unsigned* p = &As[m * AS + k4];
            p[0] = f2tf32(v.x); p[1] = f2tf32(v.y); p[2] = f2tf32(v.z); p[3] = f2tf32(v.w);
        }
        // W tile: BK x NOUT floats -> tf32 in smem.
#pragma unroll
        for (int i = tid; i < BK * NOUT / 4; i += 256) {
            int k  = i / (NOUT / 4);
            int n4 = (i % (NOUT / 4)) * 4;
            float4 v = *(const float4*)&W[(kk + k) * NOUT + n4];
            unsigned* p = &Ws[k * WS + n4];
            p[0] = f2tf32(v.x); p[1] = f2tf32(v.y); p[2] = f2tf32(v.z); p[3] = f2tf32(v.w);
        }
        __syncthreads();

#pragma unroll
        for (int kf = 0; kf < BK; kf += 8) {
            unsigned b[NFR][2];
#pragma unroll
            for (int nf = 0; nf < NFR; nf++) {
                int n0 = warp_n * WN + nf * 8 + qr;
                b[nf][0] = Ws[(kf + qc) * WS + n0];
                b[nf][1] = Ws[(kf + qc + 4) * WS + n0];
            }
#pragma unroll
            for (int mf = 0; mf < MF; mf++) {
                int m0 = warp_m * 32 + mf * 16 + qr;
                unsigned a0 = As[m0 * AS + kf + qc];
                unsigned a1 = As[(m0 + 8) * AS + kf + qc];
                unsigned a2 = As[m0 * AS + kf + qc + 4];
                unsigned a3 = As[(m0 + 8) * AS + kf + qc + 4];
#pragma unroll
                for (int nf = 0; nf < NFR; nf++) {
                    asm("mma.sync.aligned.m16n8k8.row.col.f32.tf32.tf32.f32 "
                        "{%0,%1,%2,%3}, {%4,%5,%6,%7}, {%8,%9}, {%0,%1,%2,%3};"
                        : "+f"(acc[mf][nf][0]), "+f"(acc[mf][nf][1]),
                          "+f"(acc[mf][nf][2]), "+f"(acc[mf][nf][3])
                        : "r"(a0), "r"(a1), "r"(a2), "r"(a3),
                          "r"(b[nf][0]), "r"(b[nf][1]));
                }
            }
        }
        __syncthreads();
    }

    // epilogue
#pragma unroll
    for (int mf = 0; mf < MF; mf++) {
        int r0 = br + warp_m * 32 + mf * 16 + qr;
        int r1 = r0 + 8;
#pragma unroll
        for (int nf = 0; nf < NFR; nf++) {
            int c = warp_n * WN + nf * 8 + 2 * qc;
            if (EPI == 1) {
                float bx = biass[c], by = biass[c + 1];
                if (r0 < NN) {
                    float2 o = make_float2(fmaxf(acc[mf][nf][0] + bx, 0.f),
                                           fmaxf(acc[mf][nf][1] + by, 0.f));
                    *(float2*)&((float*)out_)[r0 * NOUT + c] = o;
                }
                if (r1 < NN) {
                    float2 o = make_float2(fmaxf(acc[mf][nf][2] + bx, 0.f),
                                           fmaxf(acc[mf][nf][3] + by, 0.f));
                    *(float2*)&((float*)out_)[r1 * NOUT + c] = o;
                }
            } else {
                if (r0 < NN) {
                    __half2 h = __float22half2_rn(make_float2(acc[mf][nf][0], acc[mf][nf][1]));
                    *(__half2*)&((__half*)out_)[r0 * NOUT + c] = h;
                }
                if (r1 < NN) {
                    __half2 h = __float22half2_rn(make_float2(acc[mf][nf][2], acc[mf][nf][3]));
                    *(__half2*)&((__half*)out_)[r1 * NOUT + c] = h;
                }
            }
        }
    }
}

// ---- layer 1 fused: h1 = relu(spmm64(vZ, G1h)*AM + b1); G2h row = h1 @ W2 ----
__global__ void spmm64_g2_kernel(const __half* __restrict__ G1h, const float* __restrict__ AM,
                                 const float* __restrict__ b1, const float* __restrict__ W2,
                                 __half* __restrict__ G2h) {
    __shared__ float W2s[NH * NC];
    int tid = threadIdx.x;
    for (int i = tid; i < NH * NC; i += blockDim.x) W2s[i] = W2[i];
    __syncthreads();

    int r = blockIdx.x * (blockDim.x >> 5) + (tid >> 5);
    if (r >= NN) return;
    int lane = tid & 31;
    int s = g_rowptr[r];
    int e = g_rowptr[r + 1];
    const __half2* X = (const __half2*)G1h;   // 32 half2 per row

    float2 acc = make_float2(0.f, 0.f);
    int i = s;
    for (; i + 4 <= e; i += 4) {
        float2 e0 = __ldg(&g_eZ[i]);
        float2 e1 = __ldg(&g_eZ[i + 1]);
        float2 e2 = __ldg(&g_eZ[i + 2]);
        float2 e3 = __ldg(&g_eZ[i + 3]);
        float2 x0 = __half22float2(__ldg(&X[__float_as_int(e0.x) * 32 + lane]));
        float2 x1 = __half22float2(__ldg(&X[__float_as_int(e1.x) * 32 + lane]));
        float2 x2 = __half22float2(__ldg(&X[__float_as_int(e2.x) * 32 + lane]));
        float2 x3 = __half22float2(__ldg(&X[__float_as_int(e3.x) * 32 + lane]));
        acc.x += e0.y * x0.x; acc.y += e0.y * x0.y;
        acc.x += e1.y * x1.x; acc.y += e1.y * x1.y;
        acc.x += e2.y * x2.x; acc.y += e2.y * x2.y;
        acc.x += e3.y * x3.x; acc.y += e3.y * x3.y;
    }
    for (; i < e; i++) {
        float2 e0 = __ldg(&g_eZ[i]);
        float2 x0 = __half22float2(__ldg(&X[__float_as_int(e0.x) * 32 + lane]));
        acc.x += e0.y * x0.x; acc.y += e0.y * x0.y;
    }

    float am = __ldg(&AM[r]);
    float2 b = __ldg(&((const float2*)b1)[lane]);
    float2 hv;
    hv.x = fmaxf(acc.x * am + b.x, 0.f);
    hv.y = fmaxf(acc.y * am + b.y, 0.f);

    // G2 row = h1 @ W2   ([1,64]@[64,40])
    float acc0 = 0.f, acc1 = 0.f;
    int l8 = 32 + (lane & 7);
#pragma unroll
    for (int k = 0; k < NH; k++) {
        float hk = __shfl_sync(0xffffffffu, (k & 1) ? hv.y : hv.x, k >> 1);
        acc0 += hk * W2s[k * NC + lane];   // cols 0..31 (lane = col)
        acc1 += hk * W2s[k * NC + l8];     // cols 32..39 (valid on lanes 0..7)
    }

    // pack to half2 pairs: lanes 0..15 -> cols (2l,2l+1); lanes 16..19 -> cols (32+2(l-16), +1)
    int src0 = (lane < 16) ? (2 * lane) : (2 * (lane - 16));
    float p0 = __shfl_sync(0xffffffffu, acc0, src0);
    float p1 = __shfl_sync(0xffffffffu, acc0, src0 + 1);
    float q0 = __shfl_sync(0xffffffffu, acc1, src0);
    float q1 = __shfl_sync(0xffffffffu, acc1, src0 + 1);
    if (lane < 16) {
        ((__half2*)G2h)[r * 20 + lane] = __float22half2_rn(make_float2(p0, p1));
    } else if (lane < 20) {
        ((__half2*)G2h)[r * 20 + lane] = __float22half2_rn(make_float2(q0, q1));
    }
}

// ---- layer 2 fused: out = log_softmax(spmm40(v, G2h) + b2), one warp/row ----
__global__ void spmm40_final_kernel(const __half* __restrict__ G2h, const float* __restrict__ b2,
                                    float* __restrict__ out) {
    int tid = threadIdx.x;
    int r = blockIdx.x * (blockDim.x >> 5) + (tid >> 5);
    if (r >= NN) return;
    int lane = tid & 31;
    bool act = lane < 20;            // 20 lanes x half2 = 40 feats
    int s = g_rowptr[r];
    int e = g_rowptr[r + 1];
    const __half2* X = (const __half2*)G2h;
    int li = act ? lane : 0;

    float2 acc = make_float2(0.f, 0.f);
    int i = s;
    for (; i + 4 <= e; i += 4) {
        float2 e0 = __ldg(&g_eV[i]);
        float2 e1 = __ldg(&g_eV[i + 1]);
        float2 e2 = __ldg(&g_eV[i + 2]);
        float2 e3 = __ldg(&g_eV[i + 3]);
        float2 x0 = __half22float2(__ldg(&X[__float_as_int(e0.x) * 20 + li]));
        float2 x1 = __half22float2(__ldg(&X[__float_as_int(e1.x) * 20 + li]));
        float2 x2 = __half22float2(__ldg(&X[__float_as_int(e2.x) * 20 + li]));
        float2 x3 = __half22float2(__ldg(&X[__float_as_int(e3.x) * 20 + li]));
        acc.x += e0.y * x0.x; acc.y += e0.y * x0.y;
        acc.x += e1.y * x1.x; acc.y += e1.y * x1.y;
        acc.x += e2.y * x2.x; acc.y += e2.y * x2.y;
        acc.x += e3.y * x3.x; acc.y += e3.y * x3.y;
    }
    for (; i < e; i++) {
        float2 e0 = __ldg(&g_eV[i]);
        float2 x0 = __half22float2(__ldg(&X[__float_as_int(e0.x) * 20 + li]));
        acc.x += e0.y * x0.x; acc.y += e0.y * x0.y;
    }

    float v0 = 0.f, v1 = 0.f;
    if (act) {
        float2 b = __ldg(&((const float2*)b2)[lane]);
        v0 = acc.x + b.x;
        v1 = acc.y + b.y;
    }

    float m = act ? fmaxf(v0, v1) : -INFINITY;
#pragma unroll
    for (int o = 16; o > 0; o >>= 1) m = fmaxf(m, __shfl_xor_sync(0xffffffffu, m, o));
    float sum = act ? (expf(v0 - m) + expf(v1 - m)) : 0.f;
#pragma unroll
    for (int o = 16; o > 0; o >>= 1) sum += __shfl_xor_sync(0xffffffffu, sum, o);
    float lse = m + logf(sum);

    if (act) {
        ((float2*)out)[r * 20 + lane] = make_float2(v0 - lse, v1 - lse);
    }
}

// ---------------- launch ----------------
extern "C" void kernel_launch(void* const* d_in, const int* in_sizes, int n_in,
                              void* d_out, int out_size) {
    const float* x    = (const float*)d_in[0];
    const float* M    = (const float*)d_in[1];
    const float* AM   = (const float*)d_in[2];
    const float* adj  = (const float*)d_in[3];
    const float* adjZ = (const float*)d_in[4];
    const float* W0   = (const float*)d_in[5];
    const float* b0   = (const float*)d_in[6];
    const float* W1   = (const float*)d_in[7];
    const float* b1   = (const float*)d_in[8];
    const float* W2   = (const float*)d_in[9];
    const float* b2   = (const float*)d_in[10];
    const int*   row  = (const int*)d_in[11];
    const int*   col  = (const int*)d_in[12];
    float* out = (float*)d_out;

    void *pXh, *pAf, *pH0, *pG1h, *pG2h, *pHist;
    cudaGetSymbolAddress(&pXh,  g_xh);
    cudaGetSymbolAddress(&pAf,  g_Af);
    cudaGetSymbolAddress(&pH0,  g_H0);
    cudaGetSymbolAddress(&pG1h, g_G1h);
    cudaGetSymbolAddress(&pG2h, g_G2h);
    cudaGetSymbolAddress(&pHist, g_hist);

    // CSR build + x conversion
    cudaMemsetAsync(pHist, 0, NN * sizeof(int));
    hist_kernel<<<(EE + 255) / 256, 256>>>(row);
    tohalf_kernel<<<(NN * NF / 2 + 255) / 256, 256>>>(x, (__half2*)pXh, NN * NF / 2);
    scan_kernel<<<1, 1024>>>();
    scatter_kernel<<<(EE + 255) / 256, 256>>>(row, col, adj, adjZ, M);

    const int spmmBlocks = (NN + 7) / 8;        // 8 warps/block, 1 warp/row
    const int gemmBlocks = (NN + 127) / 128;    // BM=128

    // layer 0: H0 = relu((spmm(adjZ, M*x) * AM) @ W0 + b0)
    spmm128h_kernel<<<spmmBlocks, 256>>>((const __half*)pXh, AM, (float*)pAf);
    gemm_tf32_kernel<128, 128, 1><<<gemmBlocks, 256>>>((const float*)pAf, W0, b0, pH0);

    // layer 1 (commuted): G1h = H0 @ W1 (128->64, fp16 out), then
    //   G2h row = relu(spmm64(vZ, G1h)*AM + b1) @ W2   (fused, 64->40, fp16 out)
    gemm_tf32_kernel<128, 64, 2><<<gemmBlocks, 256>>>((const float*)pH0, W1, nullptr, pG1h);
    spmm64_g2_kernel<<<spmmBlocks, 256>>>((const __half*)pG1h, AM, b1, W2, (__half*)pG2h);

    // layer 2 (commuted): out = log_softmax(spmm40(adj, G2h) + b2)
    spmm40_final_kernel<<<spmmBlocks, 256>>>((const __half*)pG2h, b2, out);
}

// round 8
// speedup vs baseline: 1.2333x; 1.0130x over previous
#include <cuda_runtime.h>
#include <cuda_fp16.h>
#include <math.h>

#define NN 50000
#define EE 800000
#define NF 128
#define NH 64
#define NC 40

// ---- scratch (static device globals; no allocation in kernel_launch) ----
__device__ __half  g_xh[NN * NF];    // fp16 copy of x
__device__ __half  g_Ah[NN * NF];    // spmm0 output (fp16, AM folded)
__device__ __half  g_H0h[NN * NF];   // relu(A@W0+b0) (fp16)
__device__ __half  g_G1h[NN * NH];   // H0@W1 (fp16, gathered by spmm64)
__device__ __half  g_G2h[NN * NC];   // h1@W2 (fp16, gathered by spmm40)
__device__ int     g_hist[NN];
__device__ int     g_rowptr[NN + 1];
__device__ int     g_cursor[NN];
__device__ uint2   g_e8[EE];         // {vZ_f32_bits, col_u16 | v_f16<<16}

// ---------------- CSR build ----------------
__global__ void hist_kernel(const int* __restrict__ row) {
    int e = blockIdx.x * blockDim.x + threadIdx.x;
    if (e < EE) atomicAdd(&g_hist[row[e]], 1);
}

__global__ void scan_kernel() {
    __shared__ int ssum[1024];
    const int CH = (NN + 1023) / 1024;   // 49
    int t = threadIdx.x;
    int base = t * CH;
    int local = 0;
    for (int i = 0; i < CH; i++) {
        int idx = base + i;
        if (idx < NN) local += g_hist[idx];
    }
    ssum[t] = local;
    __syncthreads();
    for (int off = 1; off < 1024; off <<= 1) {
        int v = (t >= off) ? ssum[t - off] : 0;
        __syncthreads();
        ssum[t] += v;
        __syncthreads();
    }
    int run = ssum[t] - local;
    for (int i = 0; i < CH; i++) {
        int idx = base + i;
        if (idx < NN) {
            g_rowptr[idx] = run;
            g_cursor[idx] = run;
            run += g_hist[idx];
        }
    }
    if (t == 0) g_rowptr[NN] = EE;
}

__global__ void scatter_kernel(const int* __restrict__ row, const int* __restrict__ col,
                               const float* __restrict__ adj, const float* __restrict__ adjZ,
                               const float* __restrict__ M) {
    int e = blockIdx.x * blockDim.x + threadIdx.x;
    if (e >= EE) return;
    int c = col[e];
    int pos = atomicAdd(&g_cursor[row[e]], 1);
    __half vh = __float2half_rn(adj[e]);
    unsigned hi = (unsigned)(unsigned short)c | ((unsigned)__half_as_ushort(vh) << 16);
    g_e8[pos] = make_uint2(__float_as_uint(adjZ[e] * M[c]), hi);   // ONE scattered 8B store
}

// ---------------- fp32 -> fp16 convert ----------------
__global__ void tohalf_kernel(const float* __restrict__ in, __half2* __restrict__ out, int n2) {
    int i = blockIdx.x * blockDim.x + threadIdx.x;
    if (i < n2) {
        float2 v = ((const float2*)in)[i];
        out[i] = __float22half2_rn(v);
    }
}

// ---------------- SPMM 128-feat (layer 0): fp16 gathers, fp32 accum, fp16 out ----------------
__global__ void spmm128h_kernel(const __half* __restrict__ Xh, const float* __restrict__ AM,
                                __half* __restrict__ out) {
    int r = (blockIdx.x * blockDim.x + threadIdx.x) >> 5;
    if (r >= NN) return;
    int lane = threadIdx.x & 31;
    int s = g_rowptr[r];
    int e = g_rowptr[r + 1];
    const uint2* X = (const uint2*)Xh;   // 4 halves per 8B, 32 uint2 per row

    float4 acc = make_float4(0.f, 0.f, 0.f, 0.f);
    int i = s;
    for (; i + 4 <= e; i += 4) {
        uint2 e0 = __ldg(&g_e8[i]);
        uint2 e1 = __ldg(&g_e8[i + 1]);
        uint2 e2 = __ldg(&g_e8[i + 2]);
        uint2 e3 = __ldg(&g_e8[i + 3]);
        uint2 u0 = __ldg(&X[(e0.y & 0xFFFFu) * 32 + lane]);
        uint2 u1 = __ldg(&X[(e1.y & 0xFFFFu) * 32 + lane]);
        uint2 u2 = __ldg(&X[(e2.y & 0xFFFFu) * 32 + lane]);
        uint2 u3 = __ldg(&X[(e3.y & 0xFFFFu) * 32 + lane]);
        float w0 = __uint_as_float(e0.x), w1 = __uint_as_float(e1.x);
        float w2 = __uint_as_float(e2.x), w3 = __uint_as_float(e3.x);
        float2 a0 = __half22float2(*(__half2*)&u0.x), b0 = __half22float2(*(__half2*)&u0.y);
        float2 a1 = __half22float2(*(__half2*)&u1.x), b1 = __half22float2(*(__half2*)&u1.y);
        float2 a2 = __half22float2(*(__half2*)&u2.x), b2 = __half22float2(*(__half2*)&u2.y);
        float2 a3 = __half22float2(*(__half2*)&u3.x), b3 = __half22float2(*(__half2*)&u3.y);
        acc.x += w0 * a0.x; acc.y += w0 * a0.y; acc.z += w0 * b0.x; acc.w += w0 * b0.y;
        acc.x += w1 * a1.x; acc.y += w1 * a1.y; acc.z += w1 * b1.x; acc.w += w1 * b1.y;
        acc.x += w2 * a2.x; acc.y += w2 * a2.y; acc.z += w2 * b2.x; acc.w += w2 * b2.y;
        acc.x += w3 * a3.x; acc.y += w3 * a3.y; acc.z += w3 * b3.x; acc.w += w3 * b3.y;
    }
    for (; i < e; i++) {
        uint2 e0 = __ldg(&g_e8[i]);
        uint2 u0 = __ldg(&X[(e0.y & 0xFFFFu) * 32 + lane]);
        float w0 = __uint_as_float(e0.x);
        float2 a0 = __half22float2(*(__half2*)&u0.x), b0 = __half22float2(*(__half2*)&u0.y);
        acc.x += w0 * a0.x; acc.y += w0 * a0.y; acc.z += w0 * b0.x; acc.w += w0 * b0.y;
    }
    float am = __ldg(&AM[r]);
    __half2 h0 = __float22half2_rn(make_float2(acc.x * am, acc.y * am));
    __half2 h1 = __float22half2_rn(make_float2(acc.z * am, acc.w * am));
    ((uint2*)out)[r * 32 + lane] = make_uint2(*(unsigned*)&h0, *(unsigned*)&h1);
}

// ---------------- fp16 tensor-core GEMM (mma.sync m16n8k16, fp32 accum) ----------------
// EPI 1: bias+relu, fp16 out.  EPI 2: plain fp16 out.
// 256 thr (8 warps, 4x2), BM=128, BN=NOUT, BK=16.
template <int KIN, int NOUT, int EPI>
__global__ __launch_bounds__(256) void gemm_f16_kernel(
        const __half* __restrict__ A, const float* __restrict__ W,
        const float* __restrict__ bias, __half* __restrict__ out) {
    constexpr int BM = 128;
    constexpr int BK = 16;
    constexpr int AS = 24;          // As stride in halves (48B) -> conflict-free LDS.32
    constexpr int WS = 24;          // Wt stride in halves
    constexpr int WN = NOUT / 2;    // warp tile cols
    constexpr int MF = 2;           // 32 rows/warp
    constexpr int NFR = WN / 8;     // n-frags per warp (8 or 4)

    __shared__ __align__(16) __half As[BM * AS];
    __shared__ __align__(16) __half Wt[NOUT * WS];   // transposed: [n][k]
    __shared__ float biass[NOUT];

    int tid    = threadIdx.x;
    int lane   = tid & 31;
    int wid    = tid >> 5;
    int warp_m = wid & 3;
    int warp_n = wid >> 2;
    int br     = blockIdx.x * BM;
    int qr     = lane >> 2;
    int qc     = lane & 3;

    if (EPI == 1 && tid < NOUT) biass[tid] = bias[tid];

    float acc[MF][NFR][4];
#pragma unroll
    for (int i = 0; i < MF; i++)
#pragma unroll
        for (int j = 0; j < NFR; j++)
#pragma unroll
            for (int k = 0; k < 4; k++) acc[i][j][k] = 0.f;

    for (int kk = 0; kk < KIN; kk += BK) {
        // A tile: BM x BK halves, uint2 (4 halves) per load, 2 per thread
#pragma unroll
        for (int it = 0; it < (BM * BK / 4) / 256; it++) {
            int i  = tid + it * 256;
            int m  = i >> 2;             // BK/4 = 4 uint2 per row
            int c4 = (i & 3) * 4;
            int gr = br + m;
            uint2 v = make_uint2(0u, 0u);
            if (gr < NN) v = *(const uint2*)&A[gr * KIN + kk + c4];
            *(uint2*)&As[m * AS + c4] = v;
        }
        // W tile: BK x NOUT fp32 -> transposed fp16 Wt[n][k]
#pragma unroll
        for (int i = tid; i < BK * NOUT / 4; i += 256) {
            int k  = i / (NOUT / 4);
            int n4 = (i % (NOUT / 4)) * 4;
            float4 v = *(const float4*)&W[(kk + k) * NOUT + n4];
            Wt[(n4 + 0) * WS + k] = __float2half_rn(v.x);
            Wt[(n4 + 1) * WS + k] = __float2half_rn(v.y);
            Wt[(n4 + 2) * WS + k] = __float2half_rn(v.z);
            Wt[(n4 + 3) * WS + k] = __float2half_rn(v.w);
        }
        __syncthreads();

        unsigned b[NFR][2];
#pragma unroll
        for (int nf = 0; nf < NFR; nf++) {
            int n0 = warp_n * WN + nf * 8 + qr;
            b[nf][0] = *(unsigned*)&Wt[n0 * WS + 2 * qc];
            b[nf][1] = *(unsigned*)&Wt[n0 * WS + 2 * qc + 8];
        }
#pragma unroll
        for (int mf = 0; mf < MF; mf++) {
            int m0 = warp_m * 32 + mf * 16;
            unsigned a0 = *(unsigned*)&As[(m0 + qr) * AS + 2 * qc];
            unsigned a1 = *(unsigned*)&As[(m0 + qr + 8) * AS + 2 * qc];
            unsigned a2 = *(unsigned*)&As[(m0 + qr) * AS + 2 * qc + 8];
            unsigned a3 = *(unsigned*)&As[(m0 + qr + 8) * AS + 2 * qc + 8];
#pragma unroll
            for (int nf = 0; nf < NFR; nf++) {
                asm("mma.sync.aligned.m16n8k16.row.col.f32.f16.f16.f32 "
                    "{%0,%1,%2,%3}, {%4,%5,%6,%7}, {%8,%9}, {%0,%1,%2,%3};"
                    : "+f"(acc[mf][nf][0]), "+f"(acc[mf][nf][1]),
                      "+f"(acc[mf][nf][2]), "+f"(acc[mf][nf][3])
                    : "r"(a0), "r"(a1), "r"(a2), "r"(a3),
                      "r"(b[nf][0]), "r"(b[nf][1]));
            }
        }
        __syncthreads();
    }

#pragma unroll
    for (int mf = 0; mf < MF; mf++) {
        int r0 = br + warp_m * 32 + mf * 16 + qr;
        int r1 = r0 + 8;
#pragma unroll
        for (int nf = 0; nf < NFR; nf++) {
            int c = warp_n * WN + nf * 8 + 2 * qc;
            float v0 = acc[mf][nf][0], v1 = acc[mf][nf][1];
            float v2 = acc[mf][nf][2], v3 = acc[mf][nf][3];
            if (EPI == 1) {
                float bx = biass[c], by = biass[c + 1];
                v0 = fmaxf(v0 + bx, 0.f); v1 = fmaxf(v1 + by, 0.f);
                v2 = fmaxf(v2 + bx, 0.f); v3 = fmaxf(v3 + by, 0.f);
            }
            if (r0 < NN) *(__half2*)&out[r0 * NOUT + c] = __float22half2_rn(make_float2(v0, v1));
            if (r1 < NN) *(__half2*)&out[r1 * NOUT + c] = __float22half2_rn(make_float2(v2, v3));
        }
    }
}

// ---- layer 1 fused: h1 = relu(spmm64(vZ, G1h)*AM + b1); G2h row = h1 @ W2 ----
__global__ void spmm64_g2_kernel(const __half* __restrict__ G1h, const float* __restrict__ AM,
                                 const float* __restrict__ b1, const float* __restrict__ W2,
                                 __half* __restrict__ G2h) {
    __shared__ float W2s[NH * NC];
    int tid = threadIdx.x;
    for (int i = tid; i < NH * NC; i += blockDim.x) W2s[i] = W2[i];
    __syncthreads();

    int r = blockIdx.x * (blockDim.x >> 5) + (tid >> 5);
    if (r >= NN) return;
    int lane = tid & 31;
    int s = g_rowptr[r];
    int e = g_rowptr[r + 1];
    const __half2* X = (const __half2*)G1h;   // 32 half2 per row

    float2 acc = make_float2(0.f, 0.f);
    int i = s;
    for (; i + 4 <= e; i += 4) {
        uint2 e0 = __ldg(&g_e8[i]);
        uint2 e1 = __ldg(&g_e8[i + 1]);
        uint2 e2 = __ldg(&g_e8[i + 2]);
        uint2 e3 = __ldg(&g_e8[i + 3]);
        float2 x0 = __half22float2(__ldg(&X[(e0.y & 0xFFFFu) * 32 + lane]));
        float2 x1 = __half22float2(__ldg(&X[(e1.y & 0xFFFFu) * 32 + lane]));
        float2 x2 = __half22float2(__ldg(&X[(e2.y & 0xFFFFu) * 32 + lane]));
        float2 x3 = __half22float2(__ldg(&X[(e3.y & 0xFFFFu) * 32 + lane]));
        float w0 = __uint_as_float(e0.x), w1 = __uint_as_float(e1.x);
        float w2 = __uint_as_float(e2.x), w3 = __uint_as_float(e3.x);
        acc.x += w0 * x0.x; acc.y += w0 * x0.y;
        acc.x += w1 * x1.x; acc.y += w1 * x1.y;
        acc.x += w2 * x2.x; acc.y += w2 * x2.y;
        acc.x += w3 * x3.x; acc.y += w3 * x3.y;
    }
    for (; i < e; i++) {
        uint2 e0 = __ldg(&g_e8[i]);
        float2 x0 = __half22float2(__ldg(&X[(e0.y & 0xFFFFu) * 32 + lane]));
        float w0 = __uint_as_float(e0.x);
        acc.x += w0 * x0.x; acc.y += w0 * x0.y;
    }

    float am = __ldg(&AM[r]);
    float2 b = __ldg(&((const float2*)b1)[lane]);
    float2 hv;
    hv.x = fmaxf(acc.x * am + b.x, 0.f);
    hv.y = fmaxf(acc.y * am + b.y, 0.f);

    // G2 row = h1 @ W2   ([1,64]@[64,40])
    float acc0 = 0.f, acc1 = 0.f;
    int l8 = 32 + (lane & 7);
#pragma unroll
    for (int k = 0; k < NH; k++) {
        float hk = __shfl_sync(0xffffffffu, (k & 1) ? hv.y : hv.x, k >> 1);
        acc0 += hk * W2s[k * NC + lane];   // cols 0..31
        acc1 += hk * W2s[k * NC + l8];     // cols 32..39 (lanes 0..7)
    }

    int src0 = (lane < 16) ? (2 * lane) : (2 * (lane - 16));
    float p0 = __shfl_sync(0xffffffffu, acc0, src0);
    float p1 = __shfl_sync(0xffffffffu, acc0, src0 + 1);
    float q0 = __shfl_sync(0xffffffffu, acc1, src0);
    float q1 = __shfl_sync(0xffffffffu, acc1, src0 + 1);
    if (lane < 16) {
        ((__half2*)G2h)[r * 20 + lane] = __float22half2_rn(make_float2(p0, p1));
    } else if (lane < 20) {
        ((__half2*)G2h)[r * 20 + lane] = __float22half2_rn(make_float2(q0, q1));
    }
}

// ---- layer 2 fused: out = log_softmax(spmm40(v, G2h) + b2), one warp/row ----
__global__ void spmm40_final_kernel(const __half* __restrict__ G2h, const float* __restrict__ b2,
                                    float* __restrict__ out) {
    int tid = threadIdx.x;
    int r = blockIdx.x * (blockDim.x >> 5) + (tid >> 5);
    if (r >= NN) return;
    int lane = tid & 31;
    bool act = lane < 20;
    int s = g_rowptr[r];
    int e = g_rowptr[r + 1];
    const __half2* X = (const __half2*)G2h;
    int li = act ? lane : 0;

    float2 acc = make_float2(0.f, 0.f);
    int i = s;
    for (; i + 4 <= e; i += 4) {
        uint2 e0 = __ldg(&g_e8[i]);
        uint2 e1 = __ldg(&g_e8[i + 1]);
        uint2 e2 = __ldg(&g_e8[i + 2]);
        uint2 e3 = __ldg(&g_e8[i + 3]);
        float2 x0 = __half22float2(__ldg(&X[(e0.y & 0xFFFFu) * 20 + li]));
        float2 x1 = __half22float2(__ldg(&X[(e1.y & 0xFFFFu) * 20 + li]));
        float2 x2 = __half22float2(__ldg(&X[(e2.y & 0xFFFFu) * 20 + li]));
        float2 x3 = __half22float2(__ldg(&X[(e3.y & 0xFFFFu) * 20 + li]));
        float w0 = __half2float(__ushort_as_half((unsigned short)(e0.y >> 16)));
        float w1 = __half2float(__ushort_as_half((unsigned short)(e1.y >> 16)));
        float w2 = __half2float(__ushort_as_half((unsigned short)(e2.y >> 16)));
        float w3 = __half2float(__ushort_as_half((unsigned short)(e3.y >> 16)));
        acc.x += w0 * x0.x; acc.y += w0 * x0.y;
        acc.x += w1 * x1.x; acc.y += w1 * x1.y;
        acc.x += w2 * x2.x; acc.y += w2 * x2.y;
        acc.x += w3 * x3.x; acc.y += w3 * x3.y;
    }
    for (; i < e; i++) {
        uint2 e0 = __ldg(&g_e8[i]);
        float2 x0 = __half22float2(__ldg(&X[(e0.y & 0xFFFFu) * 20 + li]));
        float w0 = __half2float(__ushort_as_half((unsigned short)(e0.y >> 16)));
        acc.x += w0 * x0.x; acc.y += w0 * x0.y;
    }

    float v0 = 0.f, v1 = 0.f;
    if (act) {
        float2 b = __ldg(&((const float2*)b2)[lane]);
        v0 = acc.x + b.x;
        v1 = acc.y + b.y;
    }

    float m = act ? fmaxf(v0, v1) : -INFINITY;
#pragma unroll
    for (int o = 16; o > 0; o >>= 1) m = fmaxf(m, __shfl_xor_sync(0xffffffffu, m, o));
    float sum = act ? (expf(v0 - m) + expf(v1 - m)) : 0.f;
#pragma unroll
    for (int o = 16; o > 0; o >>= 1) sum += __shfl_xor_sync(0xffffffffu, sum, o);
    float lse = m + logf(sum);

    if (act) {
        ((float2*)out)[r * 20 + lane] = make_float2(v0 - lse, v1 - lse);
    }
}

// ---------------- launch ----------------
extern "C" void kernel_launch(void* const* d_in, const int* in_sizes, int n_in,
                              void* d_out, int out_size) {
    const float* x    = (const float*)d_in[0];
    const float* M    = (const float*)d_in[1];
    const float* AM   = (const float*)d_in[2];
    const float* adj  = (const float*)d_in[3];
    const float* adjZ = (const float*)d_in[4];
    const float* W0   = (const float*)d_in[5];
    const float* b0   = (const float*)d_in[6];
    const float* W1   = (const float*)d_in[7];
    const float* b1   = (const float*)d_in[8];
    const float* W2   = (const float*)d_in[9];
    const float* b2   = (const float*)d_in[10];
    const int*   row  = (const int*)d_in[11];
    const int*   col  = (const int*)d_in[12];
    float* out = (float*)d_out;

    void *pXh, *pAh, *pH0h, *pG1h, *pG2h, *pHist;
    cudaGetSymbolAddress(&pXh,  g_xh);
    cudaGetSymbolAddress(&pAh,  g_Ah);
    cudaGetSymbolAddress(&pH0h, g_H0h);
    cudaGetSymbolAddress(&pG1h, g_G1h);
    cudaGetSymbolAddress(&pG2h, g_G2h);
    cudaGetSymbolAddress(&pHist, g_hist);

    // CSR build + x conversion
    cudaMemsetAsync(pHist, 0, NN * sizeof(int));
    hist_kernel<<<(EE + 255) / 256, 256>>>(row);
    tohalf_kernel<<<(NN * NF / 2 + 255) / 256, 256>>>(x, (__half2*)pXh, NN * NF / 2);
    scan_kernel<<<1, 1024>>>();
    scatter_kernel<<<(EE + 255) / 256, 256>>>(row, col, adj, adjZ, M);

    const int spmmBlocks = (NN + 7) / 8;        // 8 warps/block, 1 warp/row
    const int gemmBlocks = (NN + 127) / 128;    // BM=128

    // layer 0: H0 = relu((spmm(adjZ, M*x) * AM) @ W0 + b0)
    spmm128h_kernel<<<spmmBlocks, 256>>>((const __half*)pXh, AM, (__half*)pAh);
    gemm_f16_kernel<128, 128, 1><<<gemmBlocks, 256>>>((const __half*)pAh, W0, b0, (__half*)pH0h);

    // layer 1 (commuted): G1h = H0 @ W1 (128->64), then
    //   G2h row = relu(spmm64(vZ, G1h)*AM + b1) @ W2   (fused, 64->40)
    gemm_f16_kernel<128, 64, 2><<<gemmBlocks, 256>>>((const __half*)pH0h, W1, nullptr, (__half*)pG1h);
    spmm64_g2_kernel<<<spmmBlocks, 256>>>((const __half*)pG1h, AM, b1, W2, (__half*)pG2h);

    // layer 2 (commuted): out = log_softmax(spmm40(adj, G2h) + b2)
    spmm40_final_kernel<<<spmmBlocks, 256>>>((const __half*)pG2h, b2, out);
}

// round 9
// speedup vs baseline: 1.4046x; 1.1390x over previous
#include <cuda_runtime.h>
#include <cuda_fp16.h>
#include <math.h>

#define NN 50000
#define EE 800000
#define NF 128
#define NH 64
#define NC 40

// ---- scratch (static device globals; no allocation in kernel_launch) ----
__device__ __half  g_xh[NN * NF];    // fp16 copy of x
__device__ __half  g_Ah[NN * NF];    // spmm0 output (fp16, AM folded); later reused as H1 (NN x 64)
__device__ __half  g_H0h[NN * NF];   // relu(A@W0+b0) (fp16)
__device__ __half  g_G1h[NN * NH];   // H0@W1 (fp16, gathered by spmm64)
__device__ __half  g_G2h[NN * NC];   // H1@W2 (fp16, gathered by spmm40)
__device__ int     g_hist[NN];
__device__ int     g_rowptr[NN + 1];
__device__ int     g_cursor[NN];
__device__ uint2   g_e8[EE];         // {vZ_f32_bits, col_u16 | v_f16<<16}

// ---------------- combo: hist (atomic) + x->fp16 convert, one launch ----------------
#define HIST_BLOCKS ((EE + 255) / 256)
#define CVT_BLOCKS  ((NN * NF / 2 + 255) / 256)
__global__ void hist_tohalf_kernel(const int* __restrict__ row, const float* __restrict__ x) {
    int b = blockIdx.x;
    if (b < HIST_BLOCKS) {
        int e = b * 256 + threadIdx.x;
        if (e < EE) atomicAdd(&g_hist[row[e]], 1);
    } else {
        int i = (b - HIST_BLOCKS) * 256 + threadIdx.x;
        if (i < NN * NF / 2) {
            float2 v = ((const float2*)x)[i];
            ((__half2*)g_xh)[i] = __float22half2_rn(v);
        }
    }
}

// ---------------- single-block exclusive scan ----------------
__global__ void scan_kernel() {
    __shared__ int ssum[1024];
    const int CH = (NN + 1023) / 1024;   // 49
    int t = threadIdx.x;
    int base = t * CH;
    int local = 0;
    for (int i = 0; i < CH; i++) {
        int idx = base + i;
        if (idx < NN) local += g_hist[idx];
    }
    ssum[t] = local;
    __syncthreads();
    for (int off = 1; off < 1024; off <<= 1) {
        int v = (t >= off) ? ssum[t - off] : 0;
        __syncthreads();
        ssum[t] += v;
        __syncthreads();
    }
    int run = ssum[t] - local;
    for (int i = 0; i < CH; i++) {
        int idx = base + i;
        if (idx < NN) {
            g_rowptr[idx] = run;
            g_cursor[idx] = run;
            run += g_hist[idx];
        }
    }
    if (t == 0) g_rowptr[NN] = EE;
}

__global__ void scatter_kernel(const int* __restrict__ row, const int* __restrict__ col,
                               const float* __restrict__ adj, const float* __restrict__ adjZ,
                               const float* __restrict__ M) {
    int e = blockIdx.x * blockDim.x + threadIdx.x;
    if (e >= EE) return;
    int c = col[e];
    int pos = atomicAdd(&g_cursor[row[e]], 1);
    __half vh = __float2half_rn(adj[e]);
    unsigned hi = (unsigned)(unsigned short)c | ((unsigned)__half_as_ushort(vh) << 16);
    g_e8[pos] = make_uint2(__float_as_uint(adjZ[e] * M[c]), hi);   // one scattered 8B store
}

// ---------------- SPMM 128-feat (layer 0): fp16 gathers, fp32 accum, fp16 out ----------------
__global__ void spmm128h_kernel(const __half* __restrict__ Xh, const float* __restrict__ AM,
                                __half* __restrict__ out) {
    int r = (blockIdx.x * blockDim.x + threadIdx.x) >> 5;
    if (r >= NN) return;
    int lane = threadIdx.x & 31;
    int s = g_rowptr[r];
    int e = g_rowptr[r + 1];
    const uint2* X = (const uint2*)Xh;

    float4 acc = make_float4(0.f, 0.f, 0.f, 0.f);
    int i = s;
    for (; i + 4 <= e; i += 4) {
        uint2 e0 = __ldg(&g_e8[i]);
        uint2 e1 = __ldg(&g_e8[i + 1]);
        uint2 e2 = __ldg(&g_e8[i + 2]);
        uint2 e3 = __ldg(&g_e8[i + 3]);
        uint2 u0 = __ldg(&X[(e0.y & 0xFFFFu) * 32 + lane]);
        uint2 u1 = __ldg(&X[(e1.y & 0xFFFFu) * 32 + lane]);
        uint2 u2 = __ldg(&X[(e2.y & 0xFFFFu) * 32 + lane]);
        uint2 u3 = __ldg(&X[(e3.y & 0xFFFFu) * 32 + lane]);
        float w0 = __uint_as_float(e0.x), w1 = __uint_as_float(e1.x);
        float w2 = __uint_as_float(e2.x), w3 = __uint_as_float(e3.x);
        float2 a0 = __half22float2(*(__half2*)&u0.x), b0 = __half22float2(*(__half2*)&u0.y);
        float2 a1 = __half22float2(*(__half2*)&u1.x), b1 = __half22float2(*(__half2*)&u1.y);
        float2 a2 = __half22float2(*(__half2*)&u2.x), b2 = __half22float2(*(__half2*)&u2.y);
        float2 a3 = __half22float2(*(__half2*)&u3.x), b3 = __half22float2(*(__half2*)&u3.y);
        acc.x += w0 * a0.x; acc.y += w0 * a0.y; acc.z += w0 * b0.x; acc.w += w0 * b0.y;
        acc.x += w1 * a1.x; acc.y += w1 * a1.y; acc.z += w1 * b1.x; acc.w += w1 * b1.y;
        acc.x += w2 * a2.x; acc.y += w2 * a2.y; acc.z += w2 * b2.x; acc.w += w2 * b2.y;
        acc.x += w3 * a3.x; acc.y += w3 * a3.y; acc.z += w3 * b3.x; acc.w += w3 * b3.y;
    }
    for (; i < e; i++) {
        uint2 e0 = __ldg(&g_e8[i]);
        uint2 u0 = __ldg(&X[(e0.y & 0xFFFFu) * 32 + lane]);
        float w0 = __uint_as_float(e0.x);
        float2 a0 = __half22float2(*(__half2*)&u0.x), b0 = __half22float2(*(__half2*)&u0.y);
        acc.x += w0 * a0.x; acc.y += w0 * a0.y; acc.z += w0 * b0.x; acc.w += w0 * b0.y;
    }
    float am = __ldg(&AM[r]);
    __half2 h0 = __float22half2_rn(make_float2(acc.x * am, acc.y * am));
    __half2 h1 = __float22half2_rn(make_float2(acc.z * am, acc.w * am));
    ((uint2*)out)[r * 32 + lane] = make_uint2(*(unsigned*)&h0, *(unsigned*)&h1);
}

// ---------------- fp16 tensor-core GEMM (mma.sync m16n8k16, fp32 accum) ----------------
// WARPN: warps along n (8/WARPN along m). EPI 1: bias+relu fp16 out; EPI 2: plain fp16 out.
template <int KIN, int NOUT, int WARPN, int EPI>
__global__ __launch_bounds__(256) void gemm_f16_kernel(
        const __half* __restrict__ A, const float* __restrict__ W,
        const float* __restrict__ bias, __half* __restrict__ out) {
    constexpr int BM  = 128;
    constexpr int BK  = 16;
    constexpr int AS  = 24;              // As stride (halves): conflict-free LDS.32
    constexpr int WS  = 24;              // Wt stride (halves)
    constexpr int NMW = 8 / WARPN;       // warps along m
    constexpr int MF  = BM / (16 * NMW); // m-frags per warp
    constexpr int WN  = NOUT / WARPN;    // warp tile n
    constexpr int NFR = WN / 8;          // n-frags per warp

    __shared__ __align__(16) __half As[BM * AS];
    __shared__ __align__(16) __half Wt[NOUT * WS];   // transposed: [n][k]
    __shared__ float biass[NOUT];

    int tid    = threadIdx.x;
    int lane   = tid & 31;
    int wid    = tid >> 5;
    int warp_m = wid % NMW;
    int warp_n = wid / NMW;
    int br     = blockIdx.x * BM;
    int qr     = lane >> 2;
    int qc     = lane & 3;

    if (EPI == 1 && tid < NOUT) biass[tid] = bias[tid];

    float acc[MF][NFR][4];
#pragma unroll
    for (int i = 0; i < MF; i++)
#pragma unroll
        for (int j = 0; j < NFR; j++)
#pragma unroll
            for (int k = 0; k < 4; k++) acc[i][j][k] = 0.f;

    for (int kk = 0; kk < KIN; kk += BK) {
        // A tile: BM x BK halves; uint2 (4 halves) per load
#pragma unroll
        for (int it = 0; it < (BM * BK / 4) / 256; it++) {
            int i  = tid + it * 256;
            int m  = i >> 2;
            int c4 = (i & 3) * 4;
            int gr = br + m;
            uint2 v = make_uint2(0u, 0u);
            if (gr < NN) v = *(const uint2*)&A[gr * KIN + kk + c4];
            *(uint2*)&As[m * AS + c4] = v;
        }
        // W tile: BK x NOUT fp32 -> transposed fp16 Wt[n][k]
#pragma unroll
        for (int i = tid; i < BK * NOUT / 4; i += 256) {
            int k  = i / (NOUT / 4);
            int n4 = (i % (NOUT / 4)) * 4;
            float4 v = *(const float4*)&W[(kk + k) * NOUT + n4];
            Wt[(n4 + 0) * WS + k] = __float2half_rn(v.x);
            Wt[(n4 + 1) * WS + k] = __float2half_rn(v.y);
            Wt[(n4 + 2) * WS + k] = __float2half_rn(v.z);
            Wt[(n4 + 3) * WS + k] = __float2half_rn(v.w);
        }
        __syncthreads();

        unsigned b[NFR][2];
#pragma unroll
        for (int nf = 0; nf < NFR; nf++) {
            int n0 = warp_n * WN + nf * 8 + qr;
            b[nf][0] = *(unsigned*)&Wt[n0 * WS + 2 * qc];
            b[nf][1] = *(unsigned*)&Wt[n0 * WS + 2 * qc + 8];
        }
#pragma unroll
        for (int mf = 0; mf < MF; mf++) {
            int m0 = warp_m * (16 * MF) + mf * 16;
            unsigned a0 = *(unsigned*)&As[(m0 + qr) * AS + 2 * qc];
            unsigned a1 = *(unsigned*)&As[(m0 + qr + 8) * AS + 2 * qc];
            unsigned a2 = *(unsigned*)&As[(m0 + qr) * AS + 2 * qc + 8];
            unsigned a3 = *(unsigned*)&As[(m0 + qr + 8) * AS + 2 * qc + 8];
#pragma unroll
            for (int nf = 0; nf < NFR; nf++) {
                asm("mma.sync.aligned.m16n8k16.row.col.f32.f16.f16.f32 "
                    "{%0,%1,%2,%3}, {%4,%5,%6,%7}, {%8,%9}, {%0,%1,%2,%3};"
                    : "+f"(acc[mf][nf][0]), "+f"(acc[mf][nf][1]),
                      "+f"(acc[mf][nf][2]), "+f"(acc[mf][nf][3])
                    : "r"(a0), "r"(a1), "r"(a2), "r"(a3),
                      "r"(b[nf][0]), "r"(b[nf][1]));
            }
        }
        __syncthreads();
    }

#pragma unroll
    for (int mf = 0; mf < MF; mf++) {
        int r0 = br + warp_m * (16 * MF) + mf * 16 + qr;
        int r1 = r0 + 8;
#pragma unroll
        for (int nf = 0; nf < NFR; nf++) {
            int c = warp_n * WN + nf * 8 + 2 * qc;
            float v0 = acc[mf][nf][0], v1 = acc[mf][nf][1];
            float v2 = acc[mf][nf][2], v3 = acc[mf][nf][3];
            if (EPI == 1) {
                float bx = biass[c], by = biass[c + 1];
                v0 = fmaxf(v0 + bx, 0.f); v1 = fmaxf(v1 + by, 0.f);
                v2 = fmaxf(v2 + bx, 0.f); v3 = fmaxf(v3 + by, 0.f);
            }
            if (r0 < NN) *(__half2*)&out[r0 * NOUT + c] = __float22half2_rn(make_float2(v0, v1));
            if (r1 < NN) *(__half2*)&out[r1 * NOUT + c] = __float22half2_rn(make_float2(v2, v3));
        }
    }
}

// ---- layer 1 spmm: H1 = relu(spmm64(vZ, G1h)*AM + b1), fp16 out (no shuffle GEMM) ----
__global__ void spmm64_kernel(const __half* __restrict__ G1h, const float* __restrict__ AM,
                              const float* __restrict__ b1, __half* __restrict__ H1h) {
    int tid = threadIdx.x;
    int r = blockIdx.x * (blockDim.x >> 5) + (tid >> 5);
    if (r >= NN) return;
    int lane = tid & 31;
    int s = g_rowptr[r];
    int e = g_rowptr[r + 1];
    const __half2* X = (const __half2*)G1h;   // 32 half2 per row

    float2 acc = make_float2(0.f, 0.f);
    int i = s;
    for (; i + 4 <= e; i += 4) {
        uint2 e0 = __ldg(&g_e8[i]);
        uint2 e1 = __ldg(&g_e8[i + 1]);
        uint2 e2 = __ldg(&g_e8[i + 2]);
        uint2 e3 = __ldg(&g_e8[i + 3]);
        float2 x0 = __half22float2(__ldg(&X[(e0.y & 0xFFFFu) * 32 + lane]));
        float2 x1 = __half22float2(__ldg(&X[(e1.y & 0xFFFFu) * 32 + lane]));
        float2 x2 = __half22float2(__ldg(&X[(e2.y & 0xFFFFu) * 32 + lane]));
        float2 x3 = __half22float2(__ldg(&X[(e3.y & 0xFFFFu) * 32 + lane]));
        float w0 = __uint_as_float(e0.x), w1 = __uint_as_float(e1.x);
        float w2 = __uint_as_float(e2.x), w3 = __uint_as_float(e3.x);
        acc.x += w0 * x0.x; acc.y += w0 * x0.y;
        acc.x += w1 * x1.x; acc.y += w1 * x1.y;
        acc.x += w2 * x2.x; acc.y += w2 * x2.y;
        acc.x += w3 * x3.x; acc.y += w3 * x3.y;
    }
    for (; i < e; i++) {
        uint2 e0 = __ldg(&g_e8[i]);
        float2 x0 = __half22float2(__ldg(&X[(e0.y & 0xFFFFu) * 32 + lane]));
        float w0 = __uint_as_float(e0.x);
        acc.x += w0 * x0.x; acc.y += w0 * x0.y;
    }

    float am = __ldg(&AM[r]);
    float2 b = __ldg(&((const float2*)b1)[lane]);
    float2 hv;
    hv.x = fmaxf(acc.x * am + b.x, 0.f);
    hv.y = fmaxf(acc.y * am + b.y, 0.f);
    ((__half2*)H1h)[r * 32 + lane] = __float22half2_rn(hv);
}

// ---- layer 2 fused: out = log_softmax(spmm40(v, G2h) + b2), one warp/row ----
__global__ void spmm40_final_kernel(const __half* __restrict__ G2h, const float* __restrict__ b2,
                                    float* __restrict__ out) {
    int tid = threadIdx.x;
    int r = blockIdx.x * (blockDim.x >> 5) + (tid >> 5);
    if (r >= NN) return;
    int lane = tid & 31;
    bool act = lane < 20;
    int s = g_rowptr[r];
    int e = g_rowptr[r + 1];
    const __half2* X = (const __half2*)G2h;
    int li = act ? lane : 0;

    float2 acc = make_float2(0.f, 0.f);
    int i = s;
    for (; i + 4 <= e; i += 4) {
        uint2 e0 = __ldg(&g_e8[i]);
        uint2 e1 = __ldg(&g_e8[i + 1]);
        uint2 e2 = __ldg(&g_e8[i + 2]);
        uint2 e3 = __ldg(&g_e8[i + 3]);
        float2 x0 = __half22float2(__ldg(&X[(e0.y & 0xFFFFu) * 20 + li]));
        float2 x1 = __half22float2(__ldg(&X[(e1.y & 0xFFFFu) * 20 + li]));
        float2 x2 = __half22float2(__ldg(&X[(e2.y & 0xFFFFu) * 20 + li]));
        float2 x3 = __half22float2(__ldg(&X[(e3.y & 0xFFFFu) * 20 + li]));
        float w0 = __half2float(__ushort_as_half((unsigned short)(e0.y >> 16)));
        float w1 = __half2float(__ushort_as_half((unsigned short)(e1.y >> 16)));
        float w2 = __half2float(__ushort_as_half((unsigned short)(e2.y >> 16)));
        float w3 = __half2float(__ushort_as_half((unsigned short)(e3.y >> 16)));
        acc.x += w0 * x0.x; acc.y += w0 * x0.y;
        acc.x += w1 * x1.x; acc.y += w1 * x1.y;
        acc.x += w2 * x2.x; acc.y += w2 * x2.y;
        acc.x += w3 * x3.x; acc.y += w3 * x3.y;
    }
    for (; i < e; i++) {
        uint2 e0 = __ldg(&g_e8[i]);
        float2 x0 = __half22float2(__ldg(&X[(e0.y & 0xFFFFu) * 20 + li]));
        float w0 = __half2float(__ushort_as_half((unsigned short)(e0.y >> 16)));
        acc.x += w0 * x0.x; acc.y += w0 * x0.y;
    }

    float v0 = 0.f, v1 = 0.f;
    if (act) {
        float2 b = __ldg(&((const float2*)b2)[lane]);
        v0 = acc.x + b.x;
        v1 = acc.y + b.y;
    }

    float m = act ? fmaxf(v0, v1) : -INFINITY;
#pragma unroll
    for (int o = 16; o > 0; o >>= 1) m = fmaxf(m, __shfl_xor_sync(0xffffffffu, m, o));
    float sum = act ? (expf(v0 - m) + expf(v1 - m)) : 0.f;
#pragma unroll
    for (int o = 16; o > 0; o >>= 1) sum += __shfl_xor_sync(0xffffffffu, sum, o);
    float lse = m + logf(sum);

    if (act) {
        ((float2*)out)[r * 20 + lane] = make_float2(v0 - lse, v1 - lse);
    }
}

// ---------------- launch ----------------
extern "C" void kernel_launch(void* const* d_in, const int* in_sizes, int n_in,
                              void* d_out, int out_size) {
    const float* x    = (const float*)d_in[0];
    const float* M    = (const float*)d_in[1];
    const float* AM   = (const float*)d_in[2];
    const float* adj  = (const float*)d_in[3];
    const float* adjZ = (const float*)d_in[4];
    const float* W0   = (const float*)d_in[5];
    const float* b0   = (const float*)d_in[6];
    const float* W1   = (const float*)d_in[7];
    const float* b1   = (const float*)d_in[8];
    const float* W2   = (const float*)d_in[9];
    const float* b2   = (const float*)d_in[10];
    const int*   row  = (const int*)d_in[11];
    const int*   col  = (const int*)d_in[12];
    float* out = (float*)d_out;

    void *pXh, *pAh, *pH0h, *pG1h, *pG2h, *pHist;
    cudaGetSymbolAddress(&pXh,  g_xh);
    cudaGetSymbolAddress(&pAh,  g_Ah);
    cudaGetSymbolAddress(&pH0h, g_H0h);
    cudaGetSymbolAddress(&pG1h, g_G1h);
    cudaGetSymbolAddress(&pG2h, g_G2h);
    cudaGetSymbolAddress(&pHist, g_hist);

    // CSR build + x conversion (combined)
    cudaMemsetAsync(pHist, 0, NN * sizeof(int));
    hist_tohalf_kernel<<<HIST_BLOCKS + CVT_BLOCKS, 256>>>(row, x);
    scan_kernel<<<1, 1024>>>();
    scatter_kernel<<<(EE + 255) / 256, 256>>>(row, col, adj, adjZ, M);

    const int spmmBlocks = (NN + 7) / 8;        // 8 warps/block, 1 warp/row
    const int gemmBlocks = (NN + 127) / 128;    // BM=128

    // layer 0: H0 = relu((spmm(adjZ, M*x) * AM) @ W0 + b0)
    spmm128h_kernel<<<spmmBlocks, 256>>>((const __half*)pXh, AM, (__half*)pAh);
    gemm_f16_kernel<128, 128, 2, 1><<<gemmBlocks, 256>>>((const __half*)pAh, W0, b0, (__half*)pH0h);

    // layer 1 (commuted): G1 = H0@W1; H1 = relu(spmm64(vZ,G1)*AM + b1)
    gemm_f16_kernel<128, 64, 2, 2><<<gemmBlocks, 256>>>((const __half*)pH0h, W1, nullptr, (__half*)pG1h);
    spmm64_kernel<<<spmmBlocks, 256>>>((const __half*)pG1h, AM, b1, (__half*)pAh);   // Ah := H1

    // layer 2 (commuted): G2 = H1@W2 (tensor cores, replaces shuffle GEMM), then
    //   out = log_softmax(spmm40(adj, G2) + b2)
    gemm_f16_kernel<64, 40, 1, 2><<<gemmBlocks, 256>>>((const __half*)pAh, W2, nullptr, (__half*)pG2h);
    spmm40_final_kernel<<<spmmBlocks, 256>>>((const __half*)pG2h, b2, out);
}